// round 12
// baseline (speedup 1.0000x reference)
#include <cuda_runtime.h>
#include <cuda_bf16.h>
#include <math.h>
#include <stdint.h>

// ---------------- problem constants ----------------
#define Bq   2
#define Sq   2048
#define Dq   1024
#define Hq   16
#define HDq  64
#define Mq   (Bq*Sq)          // 4096
#define NEGV (-10000.0f)

// ---------------- scratch (device globals; no allocation allowed) ----------
__device__ __nv_bfloat16 g_q_hi[Mq*Dq],  g_q_lo[Mq*Dq];
__device__ __nv_bfloat16 g_k_hi[Mq*Dq],  g_k_lo[Mq*Dq];
__device__ __nv_bfloat16 g_v_hi[Mq*Dq],  g_v_lo[Mq*Dq];
__device__ __nv_bfloat16 g_wq_hi[Dq*Dq], g_wq_lo[Dq*Dq];
__device__ __nv_bfloat16 g_wk_hi[Dq*Dq], g_wk_lo[Dq*Dq];
__device__ __nv_bfloat16 g_wv_hi[Dq*Dq], g_wv_lo[Dq*Dq];
__device__ __nv_bfloat16 g_wo_hi[Dq*Dq], g_wo_lo[Dq*Dq];
__device__ __nv_bfloat16 g_qhh[Bq*Hq*Sq*HDq], g_qhl[Bq*Hq*Sq*HDq];
__device__ __nv_bfloat16 g_khh[Bq*Hq*Sq*HDq], g_khl[Bq*Hq*Sq*HDq];
__device__ __nv_bfloat16 g_vhh[Bq*Hq*Sq*HDq], g_vhl[Bq*Hq*Sq*HDq];
__device__ __nv_bfloat16 g_c_hi[Mq*Dq], g_c_lo[Mq*Dq];

// =====================================================================
// helpers
// =====================================================================
__device__ __forceinline__ uint32_t smem_u32(const void* p) {
    uint32_t a;
    asm("{ .reg .u64 t; cvta.to.shared.u64 t, %1; cvt.u32.u64 %0, t; }"
        : "=r"(a) : "l"(p));
    return a;
}

__device__ __forceinline__ void ldsm_x4(uint32_t* r, uint32_t addr) {
    asm volatile("ldmatrix.sync.aligned.m8n8.x4.shared.b16 {%0,%1,%2,%3}, [%4];"
                 : "=r"(r[0]), "=r"(r[1]), "=r"(r[2]), "=r"(r[3]) : "r"(addr));
}
__device__ __forceinline__ void ldsm_x4t(uint32_t* r, uint32_t addr) {
    asm volatile("ldmatrix.sync.aligned.m8n8.x4.trans.shared.b16 {%0,%1,%2,%3}, [%4];"
                 : "=r"(r[0]), "=r"(r[1]), "=r"(r[2]), "=r"(r[3]) : "r"(addr));
}

__device__ __forceinline__ void mma_bf16(float* c, const uint32_t* a,
                                         const uint32_t* b) {
    asm volatile(
        "mma.sync.aligned.m16n8k16.row.col.f32.bf16.bf16.f32 "
        "{%0,%1,%2,%3}, {%4,%5,%6,%7}, {%8,%9}, {%0,%1,%2,%3};"
        : "+f"(c[0]), "+f"(c[1]), "+f"(c[2]), "+f"(c[3])
        : "r"(a[0]), "r"(a[1]), "r"(a[2]), "r"(a[3]), "r"(b[0]), "r"(b[1]));
}

__device__ __forceinline__ void cpasync16(uint32_t dst, const void* src) {
    asm volatile("cp.async.cg.shared.global [%0], [%1], 16;"
                 :: "r"(dst), "l"(src) : "memory");
}
#define CP_COMMIT() asm volatile("cp.async.commit_group;" ::: "memory")
#define CP_WAIT(n)  asm volatile("cp.async.wait_group %0;" :: "n"(n) : "memory")

// Fast exp for x <= 0 on FMA/ALU pipes only (validated round 10/11).
__device__ __forceinline__ float fexp_neg(float x) {
    x = fmaxf(x, -80.0f);
    const float y = x * 1.4426950408889634f;
    const float t = y + 12582912.0f;
    const float nf = t - 12582912.0f;
    const float f = y - nf;
    const uint32_t sbits = (__float_as_uint(t) + (127u - 0x400000u)) << 23;
    float p = 0.0013333558f;
    p = fmaf(p, f, 0.0096181291f);
    p = fmaf(p, f, 0.0555041087f);
    p = fmaf(p, f, 0.2402265069f);
    p = fmaf(p, f, 0.6931471806f);
    p = fmaf(p, f, 1.0f);
    return p * __uint_as_float(sbits);
}

__device__ __forceinline__ void split2(float x, float y, uint32_t& hi, uint32_t& lo) {
    __nv_bfloat16 hx = __float2bfloat16(x), hy = __float2bfloat16(y);
    hi = (uint32_t)__bfloat16_as_ushort(hx) |
         ((uint32_t)__bfloat16_as_ushort(hy) << 16);
    __nv_bfloat16 lx = __float2bfloat16(x - __bfloat162float(hx));
    __nv_bfloat16 ly = __float2bfloat16(y - __bfloat162float(hy));
    lo = (uint32_t)__bfloat16_as_ushort(lx) |
         ((uint32_t)__bfloat16_as_ushort(ly) << 16);
}

// =====================================================================
// fp32 -> bf16 hi/lo split
// =====================================================================
__device__ __forceinline__ void cvt_body(const float* __restrict__ x,
                                         __nv_bfloat16* __restrict__ hi,
                                         __nv_bfloat16* __restrict__ lo,
                                         int n4)
{
    int i = blockIdx.x * blockDim.x + threadIdx.x;
    if (i >= n4) return;
    float4 v = ((const float4*)x)[i];
    uint32_t h0, l0, h1, l1;
    split2(v.x, v.y, h0, l0);
    split2(v.z, v.w, h1, l1);
    ((uint2*)hi)[i] = make_uint2(h0, h1);
    ((uint2*)lo)[i] = make_uint2(l0, l1);
}

__global__ __launch_bounds__(256)
void cvt_hilo3_kernel(const float* x0, const float* x1, const float* x2,
                      __nv_bfloat16* h0, __nv_bfloat16* l0,
                      __nv_bfloat16* h1, __nv_bfloat16* l1,
                      __nv_bfloat16* h2, __nv_bfloat16* l2, int n4)
{
    const float* x; __nv_bfloat16 *hh, *ll;
    switch (blockIdx.z) {
        case 0:  x = x0; hh = h0; ll = l0; break;
        case 1:  x = x1; hh = h1; ll = l1; break;
        default: x = x2; hh = h2; ll = l2; break;
    }
    cvt_body(x, hh, ll, n4);
}

__global__ __launch_bounds__(256)
void cvt_hilo4_kernel(const float* x0, const float* x1, const float* x2, const float* x3,
                      __nv_bfloat16* h0, __nv_bfloat16* l0,
                      __nv_bfloat16* h1, __nv_bfloat16* l1,
                      __nv_bfloat16* h2, __nv_bfloat16* l2,
                      __nv_bfloat16* h3, __nv_bfloat16* l3, int n4)
{
    const float* x; __nv_bfloat16 *hh, *ll;
    switch (blockIdx.z) {
        case 0:  x = x0; hh = h0; ll = l0; break;
        case 1:  x = x1; hh = h1; ll = l1; break;
        case 2:  x = x2; hh = h2; ll = l2; break;
        default: x = x3; hh = h3; ll = l3; break;
    }
    cvt_body(x, hh, ll, n4);
}

// =====================================================================
// Tensor-core GEMM (validated rounds 9-11; unchanged):
// =====================================================================
#define GSTG 32768
#define GOFF_ALO 8192
#define GOFF_BHI 16384
#define GOFF_BLO 24576
#define GEMM_SMEM (3*GSTG)

__device__ __forceinline__
void gemm_body(char* gsm,
               const __nv_bfloat16* __restrict__ Ahi,
               const __nv_bfloat16* __restrict__ Alo,
               const __nv_bfloat16* __restrict__ Bhi,
               const __nv_bfloat16* __restrict__ Blo,
               float* __restrict__ C,
               __nv_bfloat16* __restrict__ Chi,
               __nv_bfloat16* __restrict__ Clo,
               float scale, int mode)
{
    const uint32_t sbase = smem_u32(gsm);

    const int tid  = threadIdx.x;
    const int wid  = tid >> 5;
    const int lane = tid & 31;
    const int m0 = blockIdx.y * 128;
    const int n0 = blockIdx.x * 128;
    const int wm0 = (wid & 1) * 64;
    const int wn0 = (wid >> 1) * 32;

    const int mt = lane >> 3;
    const int rr = lane & 7;
    const int a_row = rr + 8 * (mt & 1);
    const int a_kof = 8 * (mt >> 1);
    const int b_row = rr + 8 * (mt >> 1);
    const int b_kof = 8 * (mt & 1);

    const int ld_r0 = tid >> 2;
    const int ld_c0 = tid & 3;
    const int ld_r1 = ld_r0 + 64;

    float acc[4][4][4];
    #pragma unroll
    for (int i = 0; i < 4; i++)
        #pragma unroll
        for (int j = 0; j < 4; j++)
            #pragma unroll
            for (int e = 0; e < 4; e++) acc[i][j][e] = 0.0f;

    auto issue_stage = [&](int ch, int stg) {
        const int k0 = ch * 32;
        const uint32_t sst = sbase + stg * GSTG;
        {
            const int r = ld_r0, c = ld_c0;
            const uint32_t sw = (uint32_t)(r * 64 + ((c ^ ((r >> 1) & 3)) << 4));
            const size_t goA = (size_t)(m0 + r) * Dq + k0 + c * 8;
            const size_t goB = (size_t)(n0 + r) * Dq + k0 + c * 8;
            cpasync16(sst + sw,            Ahi + goA);
            cpasync16(sst + GOFF_ALO + sw, Alo + goA);
            cpasync16(sst + GOFF_BHI + sw, Bhi + goB);
            cpasync16(sst + GOFF_BLO + sw, Blo + goB);
        }
        {
            const int r = ld_r1, c = ld_c0;
            const uint32_t sw = (uint32_t)(r * 64 + ((c ^ ((r >> 1) & 3)) << 4));
            const size_t goA = (size_t)(m0 + r) * Dq + k0 + c * 8;
            const size_t goB = (size_t)(n0 + r) * Dq + k0 + c * 8;
            cpasync16(sst + sw,            Ahi + goA);
            cpasync16(sst + GOFF_ALO + sw, Alo + goA);
            cpasync16(sst + GOFF_BHI + sw, Bhi + goB);
            cpasync16(sst + GOFF_BLO + sw, Blo + goB);
        }
    };

    issue_stage(0, 0); CP_COMMIT();
    issue_stage(1, 1); CP_COMMIT();

    const int NCH = Dq / 32;   // 32
    for (int ch = 0; ch < NCH; ch++) {
        CP_WAIT(1);
        __syncthreads();
        if (ch + 2 < NCH) issue_stage(ch + 2, (ch + 2) % 3);
        CP_COMMIT();

        const uint32_t sst = sbase + (ch % 3) * GSTG;
        #pragma unroll
        for (int ks = 0; ks < 32; ks += 16) {
            uint32_t bhi[2][4], blo[2][4];
            #pragma unroll
            for (int p = 0; p < 2; p++) {
                const int row = wn0 + p * 16 + b_row;
                const int cch = (ks + b_kof) >> 3;
                const uint32_t ad = sst + GOFF_BHI +
                    (uint32_t)(row * 64 + ((cch ^ ((row >> 1) & 3)) << 4));
                ldsm_x4(bhi[p], ad);
                ldsm_x4(blo[p], ad + (GOFF_BLO - GOFF_BHI));
            }
            #pragma unroll
            for (int mf = 0; mf < 4; mf++) {
                const int row = wm0 + mf * 16 + a_row;
                const int cch = (ks + a_kof) >> 3;
                const uint32_t ad = sst +
                    (uint32_t)(row * 64 + ((cch ^ ((row >> 1) & 3)) << 4));
                uint32_t ahi[4], alo[4];
                ldsm_x4(ahi, ad);
                ldsm_x4(alo, ad + GOFF_ALO);
                #pragma unroll
                for (int nf = 0; nf < 4; nf++) {
                    const uint32_t* bh = &bhi[nf >> 1][(nf & 1) * 2];
                    const uint32_t* bl = &blo[nf >> 1][(nf & 1) * 2];
                    mma_bf16(acc[mf][nf], ahi, bh);
                    mma_bf16(acc[mf][nf], ahi, bl);
                    mma_bf16(acc[mf][nf], alo, bh);
                }
            }
        }
    }
    __syncthreads();

    const int g  = lane >> 2;
    const int cc = (lane & 3) * 2;
    #pragma unroll
    for (int mf = 0; mf < 4; mf++)
        #pragma unroll
        for (int nf = 0; nf < 4; nf++) {
            const int mA = m0 + wm0 + mf * 16 + g;
            const int nA = n0 + wn0 + nf * 8 + cc;
            #pragma unroll
            for (int half = 0; half < 2; half++) {
                const int m = mA + half * 8;
                const float vx = acc[mf][nf][half * 2];
                const float vy = acc[mf][nf][half * 2 + 1];
                if (mode == 0) {
                    *(float2*)(C + (size_t)m * Dq + nA) = make_float2(vx, vy);
                } else {
                    const int bb = m >> 11;
                    const int ss = m & (Sq - 1);
                    const int hh = nA >> 6;
                    const int hd = nA & 63;
                    const size_t idx =
                        ((size_t)(bb * Hq + hh) * Sq + ss) * HDq + hd;
                    uint32_t ph, pl;
                    split2(vx * scale, vy * scale, ph, pl);
                    *(uint32_t*)(Chi + idx) = ph;
                    *(uint32_t*)(Clo + idx) = pl;
                }
            }
        }
}

__global__ __launch_bounds__(256, 2)
void gemm_mma_kernel(const __nv_bfloat16* __restrict__ Ahi,
                     const __nv_bfloat16* __restrict__ Alo,
                     const __nv_bfloat16* __restrict__ Bhi,
                     const __nv_bfloat16* __restrict__ Blo,
                     float* __restrict__ C)
{
    extern __shared__ __align__(16) char gsm[];
    gemm_body(gsm, Ahi, Alo, Bhi, Blo, C, nullptr, nullptr, 1.0f, 0);
}

__global__ __launch_bounds__(256, 2)
void gemm_qkv_kernel(const __nv_bfloat16* qhi, const __nv_bfloat16* qlo,
                     const __nv_bfloat16* khi, const __nv_bfloat16* klo,
                     const __nv_bfloat16* vhi, const __nv_bfloat16* vlo,
                     const __nv_bfloat16* wqhi, const __nv_bfloat16* wqlo,
                     const __nv_bfloat16* wkhi, const __nv_bfloat16* wklo,
                     const __nv_bfloat16* wvhi, const __nv_bfloat16* wvlo,
                     __nv_bfloat16* qhh, __nv_bfloat16* qhl,
                     __nv_bfloat16* khh, __nv_bfloat16* khl,
                     __nv_bfloat16* vhh, __nv_bfloat16* vhl)
{
    extern __shared__ __align__(16) char gsm[];
    const __nv_bfloat16 *Ah, *Al, *Bh, *Bl;
    __nv_bfloat16 *Ch, *Cl;
    float scale;
    switch (blockIdx.z) {
        case 0:  Ah=qhi; Al=qlo; Bh=wqhi; Bl=wqlo; Ch=qhh; Cl=qhl; scale=0.125f; break;
        case 1:  Ah=khi; Al=klo; Bh=wkhi; Bl=wklo; Ch=khh; Cl=khl; scale=1.0f;   break;
        default: Ah=vhi; Al=vlo; Bh=wvhi; Bl=wvlo; Ch=vhh; Cl=vhl; scale=1.0f;   break;
    }
    gemm_body(gsm, Ah, Al, Bh, Bl, nullptr, Ch, Cl, scale, 1);
}

// =====================================================================
// Tensor-core flash attention v2:
//  - diagonal-paired q-blocks: CTA p processes qb=p AND qb=15-p
//    -> uniform 34-tile workload, 256 CTAs = 2 clean waves.
//  - 4-stage cp.async KV pipeline (prefetch distance 3).
//  - pad mask packed to 64 uint32 bit-words once per CTA.
// Exact reference masking + conditional tail phase preserved.
// =====================================================================
#define AOFF_QLO 16384
#define AOFF_KV  32768
#define AKV_STG  32768
#define AOFF_KLO 8192
#define AOFF_VHI 16384
#define AOFF_VLO 24576
#define AOFF_PAD 163840
#define ATT_SMEM 172032

__global__ __launch_bounds__(256, 1)
void attn_kernel(const __nv_bfloat16* __restrict__ qhh, const __nv_bfloat16* __restrict__ qhl,
                 const __nv_bfloat16* __restrict__ khh, const __nv_bfloat16* __restrict__ khl,
                 const __nv_bfloat16* __restrict__ vhh, const __nv_bfloat16* __restrict__ vhl,
                 const int* __restrict__ attn_mask,
                 const int* __restrict__ mask_future_p,
                 __nv_bfloat16* __restrict__ chi, __nv_bfloat16* __restrict__ clo)
{
    extern __shared__ __align__(16) char smemb[];
    const uint32_t sb = smem_u32(smemb);
    __shared__ float wred[8];
    __shared__ int s_needtail;
    __shared__ uint32_t padbits[64];

    const int tid  = threadIdx.x;
    const int wid  = tid >> 5;
    const int lane = tid & 31;
    const int bh = blockIdx.y;            // b*H + h
    const int b  = bh >> 4;
    const int h  = bh & 15;
    const int pairp = blockIdx.x;         // 0..7
    const int g  = lane >> 2;
    const int qd = lane & 3;
    const int mt = lane >> 3;
    const int rr = lane & 7;
    const int mask_future = mask_future_p[0];
    const int ntiles = Sq / 64;           // 32

    // pad mask: its own (oldest) cp.async group
    #pragma unroll
    for (int k2 = 0; k2 < 2; k2++) {
        const int chunk = tid + k2 * 256;
        cpasync16(sb + AOFF_PAD + chunk * 16,
                  attn_mask + (size_t)b * Sq + chunk * 4);
    }
    CP_COMMIT();
    bool padpacked = false;

    auto issue_kv = [&](int t, int s) {
        const int kv0 = t * 64;
        const uint32_t dst0 = sb + AOFF_KV + s * AKV_STG;
        #pragma unroll
        for (int j = 0; j < 8; j++) {
            const int idx = tid + j * 256;
            const int arr = idx >> 9;
            const int e = idx & 511;
            const int r = e >> 3, c = e & 7;
            const __nv_bfloat16* base =
                (arr == 0) ? khh : (arr == 1) ? khl : (arr == 2) ? vhh : vhl;
            const __nv_bfloat16* src = base + ((size_t)bh * Sq + kv0 + r) * HDq + c * 8;
            cpasync16(dst0 + arr * 8192 + r * 128 + ((c ^ (r & 7)) << 4), src);
        }
    };

    for (int sub = 0; sub < 2; sub++) {
        const int qb = sub ? (15 - pairp) : pairp;
        const int qr0 = qb * 128;

        __syncthreads();   // all warps done with previous sub's smem

        // Q tiles group
        #pragma unroll
        for (int j = 0; j < 8; j++) {
            const int idx = tid + j * 256;
            const int sel = idx >> 10;
            const int e = idx & 1023;
            const int r = e >> 3, c = e & 7;
            const __nv_bfloat16* src = (sel ? qhl : qhh) +
                ((size_t)bh * Sq + qr0 + r) * HDq + c * 8;
            cpasync16(sb + sel * 16384 + r * 128 + ((c ^ (r & 7)) << 4), src);
        }
        CP_COMMIT();

        float m_[2] = {-1e30f, -1e30f};
        float l_[2] = {0.0f, 0.0f};
        float Of[8][4];
        #pragma unroll
        for (int j = 0; j < 8; j++)
            #pragma unroll
            for (int e = 0; e < 4; e++) Of[j][e] = 0.0f;
        uint32_t qfh[4][4], qfl[4][4];
        bool qloaded = false;

        const int limit = mask_future ? (2 * qb + 2) : ntiles;

        for (int phase = 0; phase < 2; phase++) {
            int t0, t1;
            if (phase == 0) { t0 = 0; t1 = limit; }
            else {
                if (!mask_future || limit >= ntiles) break;
                float mymin = fminf(m_[0], m_[1]);
                #pragma unroll
                for (int off = 16; off > 0; off >>= 1)
                    mymin = fminf(mymin, __shfl_xor_sync(0xffffffffu, mymin, off));
                __syncthreads();
                if (lane == 0) wred[wid] = mymin;
                __syncthreads();
                if (tid == 0) {
                    float mn = wred[0];
                    #pragma unroll
                    for (int w = 1; w < 8; w++) mn = fminf(mn, wred[w]);
                    s_needtail = (mn < -5000.0f) ? 1 : 0;
                }
                __syncthreads();
                if (!s_needtail) break;
                t0 = limit; t1 = ntiles;
            }

            // prologue: 3 KV groups in flight
            #pragma unroll
            for (int pk = 0; pk < 3; pk++) {
                if (t0 + pk < t1) issue_kv(t0 + pk, pk);
                CP_COMMIT();
            }

            for (int i = t0; i < t1; i++) {
                CP_WAIT(2);
                __syncthreads();
                if (!padpacked) {
                    if (tid < 64) {
                        const int* pz = (const int*)(smemb + AOFF_PAD) + tid * 32;
                        uint32_t w = 0;
                        #pragma unroll
                        for (int bb2 = 0; bb2 < 32; bb2++)
                            w |= (pz[bb2] ? 1u : 0u) << bb2;
                        padbits[tid] = w;
                    }
                    __syncthreads();
                    padpacked = true;
                }
                if (!qloaded) {
                    #pragma unroll
                    for (int ks = 0; ks < 4; ks++) {
                        const int qrow = wid * 16 + rr + 8 * (mt & 1);
                        const int kch = 2 * ks + (mt >> 1);
                        const uint32_t ad = sb + qrow * 128 + ((kch ^ (qrow & 7)) << 4);
                        ldsm_x4(qfh[ks], ad);
                        ldsm_x4(qfl[ks], ad + AOFF_QLO);
                    }
                    qloaded = true;
                }
                if (i + 3 < t1) issue_kv(i + 3, (i - t0 + 3) & 3);
                CP_COMMIT();

                const uint32_t kb = sb + AOFF_KV + ((i - t0) & 3) * AKV_STG;
                const int kv0 = i * 64;

                // ---- S = Q K^T (hi/lo 3-pass) ----
                float cacc[8][4];
                #pragma unroll
                for (int j = 0; j < 8; j++)
                    #pragma unroll
                    for (int e = 0; e < 4; e++) cacc[j][e] = 0.0f;

                #pragma unroll
                for (int ks = 0; ks < 4; ks++) {
                    #pragma unroll
                    for (int np = 0; np < 4; np++) {
                        const int brow = np * 16 + rr + 8 * (mt >> 1);
                        const int kch = 2 * ks + (mt & 1);
                        const uint32_t ad = kb + brow * 128 + ((kch ^ (brow & 7)) << 4);
                        uint32_t k4h[4], k4l[4];
                        ldsm_x4(k4h, ad);
                        ldsm_x4(k4l, ad + AOFF_KLO);
                        mma_bf16(cacc[2*np],   qfh[ks], &k4h[0]);
                        mma_bf16(cacc[2*np],   qfh[ks], &k4l[0]);
                        mma_bf16(cacc[2*np],   qfl[ks], &k4h[0]);
                        mma_bf16(cacc[2*np+1], qfh[ks], &k4h[2]);
                        mma_bf16(cacc[2*np+1], qfh[ks], &k4l[2]);
                        mma_bf16(cacc[2*np+1], qfl[ks], &k4h[2]);
                    }
                }

                // ---- mask (causal add then pad replace; bitmask words) ----
                const int row0 = qr0 + wid * 16 + g;
                const int row1 = row0 + 8;
                const uint32_t wA = padbits[2 * i];
                const uint32_t wB = padbits[2 * i + 1];
                #pragma unroll
                for (int j = 0; j < 8; j++) {
                    const int cl = 8 * j + 2 * qd;           // 0..62, even
                    const int col0 = kv0 + cl;
                    float s0 = cacc[j][0], s1 = cacc[j][1];
                    float s2 = cacc[j][2], s3 = cacc[j][3];
                    if (mask_future) {
                        if (col0 > row0)     s0 += NEGV;
                        if (col0 + 1 > row0) s1 += NEGV;
                        if (col0 > row1)     s2 += NEGV;
                        if (col0 + 1 > row1) s3 += NEGV;
                    }
                    const uint32_t w = (cl & 32) ? wB : wA;
                    const int sh = cl & 31;
                    if (!((w >> sh) & 1u))       { s0 = NEGV; s2 = NEGV; }
                    if (!((w >> (sh + 1)) & 1u)) { s1 = NEGV; s3 = NEGV; }
                    cacc[j][0] = s0; cacc[j][1] = s1;
                    cacc[j][2] = s2; cacc[j][3] = s3;
                }

                // ---- online softmax ----
                float mx0 = -1e30f, mx1 = -1e30f;
                #pragma unroll
                for (int j = 0; j < 8; j++) {
                    mx0 = fmaxf(mx0, fmaxf(cacc[j][0], cacc[j][1]));
                    mx1 = fmaxf(mx1, fmaxf(cacc[j][2], cacc[j][3]));
                }
                #pragma unroll
                for (int off = 1; off <= 2; off <<= 1) {
                    mx0 = fmaxf(mx0, __shfl_xor_sync(0xffffffffu, mx0, off));
                    mx1 = fmaxf(mx1, __shfl_xor_sync(0xffffffffu, mx1, off));
                }
                const float mn0 = fmaxf(m_[0], mx0);
                const float mn1 = fmaxf(m_[1], mx1);
                const float al0 = fexp_neg(m_[0] - mn0);
                const float al1 = fexp_neg(m_[1] - mn1);
                float rs0 = 0.0f, rs1 = 0.0f;
                #pragma unroll
                for (int j = 0; j < 8; j++) {
                    const float p0 = fexp_neg(cacc[j][0] - mn0);
                    const float p1 = fexp_neg(cacc[j][1] - mn0);
                    const float p2 = fexp_neg(cacc[j][2] - mn1);
                    const float p3 = fexp_neg(cacc[j][3] - mn1);
                    cacc[j][0] = p0; cacc[j][1] = p1;
                    cacc[j][2] = p2; cacc[j][3] = p3;
                    rs0 += p0 + p1; rs1 += p2 + p3;
                }
                #pragma unroll
                for (int off = 1; off <= 2; off <<= 1) {
                    rs0 += __shfl_xor_sync(0xffffffffu, rs0, off);
                    rs1 += __shfl_xor_sync(0xffffffffu, rs1, off);
                }
                l_[0] = l_[0] * al0 + rs0;  m_[0] = mn0;
                l_[1] = l_[1] * al1 + rs1;  m_[1] = mn1;
                #pragma unroll
                for (int j = 0; j < 8; j++) {
                    Of[j][0] *= al0; Of[j][1] *= al0;
                    Of[j][2] *= al1; Of[j][3] *= al1;
                }

                // ---- O += P V (hi/lo 3-pass) ----
                const uint32_t vb = kb + AOFF_VHI;
                #pragma unroll
                for (int ks = 0; ks < 4; ks++) {
                    uint32_t pah[4], pal[4];
                    split2(cacc[2*ks][0],   cacc[2*ks][1],   pah[0], pal[0]);
                    split2(cacc[2*ks][2],   cacc[2*ks][3],   pah[1], pal[1]);
                    split2(cacc[2*ks+1][0], cacc[2*ks+1][1], pah[2], pal[2]);
                    split2(cacc[2*ks+1][2], cacc[2*ks+1][3], pah[3], pal[3]);
                    #pragma unroll
                    for (int np = 0; np < 4; np++) {
                        const int kvr = ks * 16 + rr + 8 * (mt & 1);
                        const int nch = 2 * np + (mt >> 1);
                        const uint32_t ad = vb + kvr * 128 + ((nch ^ (kvr & 7)) << 4);
                        uint32_t v4h[4], v4l[4];
                        ldsm_x4t(v4h, ad);
                        ldsm_x4t(v4l, ad + (AOFF_VLO - AOFF_VHI));
                        mma_bf16(Of[2*np],   pah, &v4h[0]);
                        mma_bf16(Of[2*np],   pah, &v4l[0]);
                        mma_bf16(Of[2*np],   pal, &v4h[0]);
                        mma_bf16(Of[2*np+1], pah, &v4h[2]);
                        mma_bf16(Of[2*np+1], pah, &v4l[2]);
                        mma_bf16(Of[2*np+1], pal, &v4h[2]);
                    }
                }
            }
        }

        // ---- epilogue for this q-block ----
        const float inv0 = 1.0f / l_[0];
        const float inv1 = 1.0f / l_[1];
        const int row0 = qr0 + wid * 16 + g;
        const int row1 = row0 + 8;
        #pragma unroll
        for (int jo = 0; jo < 8; jo++) {
            const int col = h * HDq + 8 * jo + 2 * qd;
            const size_t i0 = ((size_t)b * Sq + row0) * Dq + col;
            const size_t i1 = ((size_t)b * Sq + row1) * Dq + col;
            uint32_t ph, pl;
            split2(Of[jo][0] * inv0, Of[jo][1] * inv0, ph, pl);
            *(uint32_t*)(chi + i0) = ph;
            *(uint32_t*)(clo + i0) = pl;
            split2(Of[jo][2] * inv1, Of[jo][3] * inv1, ph, pl);
            *(uint32_t*)(chi + i1) = ph;
            *(uint32_t*)(clo + i1) = pl;
        }
    }
}

// =====================================================================
// launch
// =====================================================================
extern "C" void kernel_launch(void* const* d_in, const int* in_sizes, int n_in,
                              void* d_out, int out_size)
{
    const float* q   = (const float*)d_in[0];
    const float* k   = (const float*)d_in[1];
    const float* v   = (const float*)d_in[2];
    const int*   am  = (const int*)  d_in[3];
    const float* Wq  = (const float*)d_in[4];
    const float* Wk  = (const float*)d_in[5];
    const float* Wv  = (const float*)d_in[6];
    const float* Wo  = (const float*)d_in[7];
    const int*   mf  = (const int*)  d_in[8];
    float* out = (float*)d_out;

    __nv_bfloat16 *qhi, *qlo, *khi, *klo, *vhi, *vlo;
    __nv_bfloat16 *wqhi, *wqlo, *wkhi, *wklo, *wvhi, *wvlo, *wohi, *wolo;
    __nv_bfloat16 *qhh, *qhl, *khh, *khl, *vhh, *vhl, *chi, *clo;
    cudaGetSymbolAddress((void**)&qhi,  g_q_hi);  cudaGetSymbolAddress((void**)&qlo,  g_q_lo);
    cudaGetSymbolAddress((void**)&khi,  g_k_hi);  cudaGetSymbolAddress((void**)&klo,  g_k_lo);
    cudaGetSymbolAddress((void**)&vhi,  g_v_hi);  cudaGetSymbolAddress((void**)&vlo,  g_v_lo);
    cudaGetSymbolAddress((void**)&wqhi, g_wq_hi); cudaGetSymbolAddress((void**)&wqlo, g_wq_lo);
    cudaGetSymbolAddress((void**)&wkhi, g_wk_hi); cudaGetSymbolAddress((void**)&wklo, g_wk_lo);
    cudaGetSymbolAddress((void**)&wvhi, g_wv_hi); cudaGetSymbolAddress((void**)&wvlo, g_wv_lo);
    cudaGetSymbolAddress((void**)&wohi, g_wo_hi); cudaGetSymbolAddress((void**)&wolo, g_wo_lo);
    cudaGetSymbolAddress((void**)&qhh,  g_qhh);   cudaGetSymbolAddress((void**)&qhl,  g_qhl);
    cudaGetSymbolAddress((void**)&khh,  g_khh);   cudaGetSymbolAddress((void**)&khl,  g_khl);
    cudaGetSymbolAddress((void**)&vhh,  g_vhh);   cudaGetSymbolAddress((void**)&vhl,  g_vhl);
    cudaGetSymbolAddress((void**)&chi,  g_c_hi);  cudaGetSymbolAddress((void**)&clo,  g_c_lo);

    cudaFuncSetAttribute(gemm_mma_kernel,
                         cudaFuncAttributeMaxDynamicSharedMemorySize, GEMM_SMEM);
    cudaFuncSetAttribute(gemm_qkv_kernel,
                         cudaFuncAttributeMaxDynamicSharedMemorySize, GEMM_SMEM);
    cudaFuncSetAttribute(attn_kernel,
                         cudaFuncAttributeMaxDynamicSharedMemorySize, ATT_SMEM);

    // 1) hi/lo conversions
    const int nIn4 = Mq * Dq / 4;
    const int nW4  = Dq * Dq / 4;
    {
        dim3 g3(nIn4 / 256, 1, 3);
        cvt_hilo3_kernel<<<g3, 256>>>(q, k, v, qhi, qlo, khi, klo, vhi, vlo, nIn4);
        dim3 g4(nW4 / 256, 1, 4);
        cvt_hilo4_kernel<<<g4, 256>>>(Wq, Wk, Wv, Wo,
                                      wqhi, wqlo, wkhi, wklo,
                                      wvhi, wvlo, wohi, wolo, nW4);
    }

    // 2) fused QKV projections -> bf16 hi/lo head-split (Q pre-scaled 1/8)
    dim3 qkv_grid(Dq / 128, Mq / 128, 3);
    gemm_qkv_kernel<<<qkv_grid, 256, GEMM_SMEM>>>(
        qhi, qlo, khi, klo, vhi, vlo,
        wqhi, wqlo, wkhi, wklo, wvhi, wvlo,
        qhh, qhl, khh, khl, vhh, vhl);

    // 3) tensor-core flash attention (diagonal-paired) -> ctx hi/lo bf16
    dim3 attn_grid(8, Bq * Hq);    // 256 CTAs, uniform 34-tile workload
    attn_kernel<<<attn_grid, 256, ATT_SMEM>>>(
        qhh, qhl, khh, khl, vhh, vhl, am, mf, chi, clo);

    // 4) output projection
    dim3 gemm_grid(Dq / 128, Mq / 128);
    gemm_mma_kernel<<<gemm_grid, 256, GEMM_SMEM>>>(chi, clo, wohi, wolo, out);
}

// round 14
// speedup vs baseline: 1.0945x; 1.0945x over previous
#include <cuda_runtime.h>
#include <cuda_bf16.h>
#include <math.h>
#include <stdint.h>

// ---------------- problem constants ----------------
#define Bq   2
#define Sq   2048
#define Dq   1024
#define Hq   16
#define HDq  64
#define Mq   (Bq*Sq)          // 4096
#define NEGV (-10000.0f)

// ---------------- scratch (device globals; no allocation allowed) ----------
__device__ __nv_bfloat16 g_q_hi[Mq*Dq],  g_q_lo[Mq*Dq];
__device__ __nv_bfloat16 g_k_hi[Mq*Dq],  g_k_lo[Mq*Dq];
__device__ __nv_bfloat16 g_v_hi[Mq*Dq],  g_v_lo[Mq*Dq];
__device__ __nv_bfloat16 g_wq_hi[Dq*Dq], g_wq_lo[Dq*Dq];
__device__ __nv_bfloat16 g_wk_hi[Dq*Dq], g_wk_lo[Dq*Dq];
__device__ __nv_bfloat16 g_wv_hi[Dq*Dq], g_wv_lo[Dq*Dq];
__device__ __nv_bfloat16 g_wo_hi[Dq*Dq], g_wo_lo[Dq*Dq];
__device__ __nv_bfloat16 g_qhh[Bq*Hq*Sq*HDq], g_qhl[Bq*Hq*Sq*HDq];
__device__ __nv_bfloat16 g_khh[Bq*Hq*Sq*HDq], g_khl[Bq*Hq*Sq*HDq];
__device__ __nv_bfloat16 g_vhh[Bq*Hq*Sq*HDq], g_vhl[Bq*Hq*Sq*HDq];
__device__ __nv_bfloat16 g_c_hi[Mq*Dq], g_c_lo[Mq*Dq];

// =====================================================================
// helpers
// =====================================================================
__device__ __forceinline__ uint32_t smem_u32(const void* p) {
    uint32_t a;
    asm("{ .reg .u64 t; cvta.to.shared.u64 t, %1; cvt.u32.u64 %0, t; }"
        : "=r"(a) : "l"(p));
    return a;
}

__device__ __forceinline__ void ldsm_x4(uint32_t* r, uint32_t addr) {
    asm volatile("ldmatrix.sync.aligned.m8n8.x4.shared.b16 {%0,%1,%2,%3}, [%4];"
                 : "=r"(r[0]), "=r"(r[1]), "=r"(r[2]), "=r"(r[3]) : "r"(addr));
}
__device__ __forceinline__ void ldsm_x4t(uint32_t* r, uint32_t addr) {
    asm volatile("ldmatrix.sync.aligned.m8n8.x4.trans.shared.b16 {%0,%1,%2,%3}, [%4];"
                 : "=r"(r[0]), "=r"(r[1]), "=r"(r[2]), "=r"(r[3]) : "r"(addr));
}

__device__ __forceinline__ void mma_bf16(float* c, const uint32_t* a,
                                         const uint32_t* b) {
    asm volatile(
        "mma.sync.aligned.m16n8k16.row.col.f32.bf16.bf16.f32 "
        "{%0,%1,%2,%3}, {%4,%5,%6,%7}, {%8,%9}, {%0,%1,%2,%3};"
        : "+f"(c[0]), "+f"(c[1]), "+f"(c[2]), "+f"(c[3])
        : "r"(a[0]), "r"(a[1]), "r"(a[2]), "r"(a[3]), "r"(b[0]), "r"(b[1]));
}

__device__ __forceinline__ void cpasync16(uint32_t dst, const void* src) {
    asm volatile("cp.async.cg.shared.global [%0], [%1], 16;"
                 :: "r"(dst), "l"(src) : "memory");
}
#define CP_COMMIT() asm volatile("cp.async.commit_group;" ::: "memory")
#define CP_WAIT(n)  asm volatile("cp.async.wait_group %0;" :: "n"(n) : "memory")

// Fast exp for x <= 0 on FMA/ALU pipes only (validated rounds 10-12).
__device__ __forceinline__ float fexp_neg(float x) {
    x = fmaxf(x, -80.0f);
    const float y = x * 1.4426950408889634f;
    const float t = y + 12582912.0f;
    const float nf = t - 12582912.0f;
    const float f = y - nf;
    const uint32_t sbits = (__float_as_uint(t) + (127u - 0x400000u)) << 23;
    float p = 0.0013333558f;
    p = fmaf(p, f, 0.0096181291f);
    p = fmaf(p, f, 0.0555041087f);
    p = fmaf(p, f, 0.2402265069f);
    p = fmaf(p, f, 0.6931471806f);
    p = fmaf(p, f, 1.0f);
    return p * __uint_as_float(sbits);
}

__device__ __forceinline__ void split2(float x, float y, uint32_t& hi, uint32_t& lo) {
    __nv_bfloat16 hx = __float2bfloat16(x), hy = __float2bfloat16(y);
    hi = (uint32_t)__bfloat16_as_ushort(hx) |
         ((uint32_t)__bfloat16_as_ushort(hy) << 16);
    __nv_bfloat16 lx = __float2bfloat16(x - __bfloat162float(hx));
    __nv_bfloat16 ly = __float2bfloat16(y - __bfloat162float(hy));
    lo = (uint32_t)__bfloat16_as_ushort(lx) |
         ((uint32_t)__bfloat16_as_ushort(ly) << 16);
}

// =====================================================================
// fp32 -> bf16 hi/lo split
// =====================================================================
__device__ __forceinline__ void cvt_body(const float* __restrict__ x,
                                         __nv_bfloat16* __restrict__ hi,
                                         __nv_bfloat16* __restrict__ lo,
                                         int n4)
{
    int i = blockIdx.x * blockDim.x + threadIdx.x;
    if (i >= n4) return;
    float4 v = ((const float4*)x)[i];
    uint32_t h0, l0, h1, l1;
    split2(v.x, v.y, h0, l0);
    split2(v.z, v.w, h1, l1);
    ((uint2*)hi)[i] = make_uint2(h0, h1);
    ((uint2*)lo)[i] = make_uint2(l0, l1);
}

__global__ __launch_bounds__(256)
void cvt_hilo3_kernel(const float* x0, const float* x1, const float* x2,
                      __nv_bfloat16* h0, __nv_bfloat16* l0,
                      __nv_bfloat16* h1, __nv_bfloat16* l1,
                      __nv_bfloat16* h2, __nv_bfloat16* l2, int n4)
{
    const float* x; __nv_bfloat16 *hh, *ll;
    switch (blockIdx.z) {
        case 0:  x = x0; hh = h0; ll = l0; break;
        case 1:  x = x1; hh = h1; ll = l1; break;
        default: x = x2; hh = h2; ll = l2; break;
    }
    cvt_body(x, hh, ll, n4);
}

__global__ __launch_bounds__(256)
void cvt_hilo4_kernel(const float* x0, const float* x1, const float* x2, const float* x3,
                      __nv_bfloat16* h0, __nv_bfloat16* l0,
                      __nv_bfloat16* h1, __nv_bfloat16* l1,
                      __nv_bfloat16* h2, __nv_bfloat16* l2,
                      __nv_bfloat16* h3, __nv_bfloat16* l3, int n4)
{
    const float* x; __nv_bfloat16 *hh, *ll;
    switch (blockIdx.z) {
        case 0:  x = x0; hh = h0; ll = l0; break;
        case 1:  x = x1; hh = h1; ll = l1; break;
        case 2:  x = x2; hh = h2; ll = l2; break;
        default: x = x3; hh = h3; ll = l3; break;
    }
    cvt_body(x, hh, ll, n4);
}

// =====================================================================
// Tensor-core GEMM (validated rounds 9-12; unchanged):
// =====================================================================
#define GSTG 32768
#define GOFF_ALO 8192
#define GOFF_BHI 16384
#define GOFF_BLO 24576
#define GEMM_SMEM (3*GSTG)

__device__ __forceinline__
void gemm_body(char* gsm,
               const __nv_bfloat16* __restrict__ Ahi,
               const __nv_bfloat16* __restrict__ Alo,
               const __nv_bfloat16* __restrict__ Bhi,
               const __nv_bfloat16* __restrict__ Blo,
               float* __restrict__ C,
               __nv_bfloat16* __restrict__ Chi,
               __nv_bfloat16* __restrict__ Clo,
               float scale, int mode)
{
    const uint32_t sbase = smem_u32(gsm);

    const int tid  = threadIdx.x;
    const int wid  = tid >> 5;
    const int lane = tid & 31;
    const int m0 = blockIdx.y * 128;
    const int n0 = blockIdx.x * 128;
    const int wm0 = (wid & 1) * 64;
    const int wn0 = (wid >> 1) * 32;

    const int mt = lane >> 3;
    const int rr = lane & 7;
    const int a_row = rr + 8 * (mt & 1);
    const int a_kof = 8 * (mt >> 1);
    const int b_row = rr + 8 * (mt >> 1);
    const int b_kof = 8 * (mt & 1);

    const int ld_r0 = tid >> 2;
    const int ld_c0 = tid & 3;
    const int ld_r1 = ld_r0 + 64;

    float acc[4][4][4];
    #pragma unroll
    for (int i = 0; i < 4; i++)
        #pragma unroll
        for (int j = 0; j < 4; j++)
            #pragma unroll
            for (int e = 0; e < 4; e++) acc[i][j][e] = 0.0f;

    auto issue_stage = [&](int ch, int stg) {
        const int k0 = ch * 32;
        const uint32_t sst = sbase + stg * GSTG;
        {
            const int r = ld_r0, c = ld_c0;
            const uint32_t sw = (uint32_t)(r * 64 + ((c ^ ((r >> 1) & 3)) << 4));
            const size_t goA = (size_t)(m0 + r) * Dq + k0 + c * 8;
            const size_t goB = (size_t)(n0 + r) * Dq + k0 + c * 8;
            cpasync16(sst + sw,            Ahi + goA);
            cpasync16(sst + GOFF_ALO + sw, Alo + goA);
            cpasync16(sst + GOFF_BHI + sw, Bhi + goB);
            cpasync16(sst + GOFF_BLO + sw, Blo + goB);
        }
        {
            const int r = ld_r1, c = ld_c0;
            const uint32_t sw = (uint32_t)(r * 64 + ((c ^ ((r >> 1) & 3)) << 4));
            const size_t goA = (size_t)(m0 + r) * Dq + k0 + c * 8;
            const size_t goB = (size_t)(n0 + r) * Dq + k0 + c * 8;
            cpasync16(sst + sw,            Ahi + goA);
            cpasync16(sst + GOFF_ALO + sw, Alo + goA);
            cpasync16(sst + GOFF_BHI + sw, Bhi + goB);
            cpasync16(sst + GOFF_BLO + sw, Blo + goB);
        }
    };

    issue_stage(0, 0); CP_COMMIT();
    issue_stage(1, 1); CP_COMMIT();

    const int NCH = Dq / 32;   // 32
    for (int ch = 0; ch < NCH; ch++) {
        CP_WAIT(1);
        __syncthreads();
        if (ch + 2 < NCH) issue_stage(ch + 2, (ch + 2) % 3);
        CP_COMMIT();

        const uint32_t sst = sbase + (ch % 3) * GSTG;
        #pragma unroll
        for (int ks = 0; ks < 32; ks += 16) {
            uint32_t bhi[2][4], blo[2][4];
            #pragma unroll
            for (int p = 0; p < 2; p++) {
                const int row = wn0 + p * 16 + b_row;
                const int cch = (ks + b_kof) >> 3;
                const uint32_t ad = sst + GOFF_BHI +
                    (uint32_t)(row * 64 + ((cch ^ ((row >> 1) & 3)) << 4));
                ldsm_x4(bhi[p], ad);
                ldsm_x4(blo[p], ad + (GOFF_BLO - GOFF_BHI));
            }
            #pragma unroll
            for (int mf = 0; mf < 4; mf++) {
                const int row = wm0 + mf * 16 + a_row;
                const int cch = (ks + a_kof) >> 3;
                const uint32_t ad = sst +
                    (uint32_t)(row * 64 + ((cch ^ ((row >> 1) & 3)) << 4));
                uint32_t ahi[4], alo[4];
                ldsm_x4(ahi, ad);
                ldsm_x4(alo, ad + GOFF_ALO);
                #pragma unroll
                for (int nf = 0; nf < 4; nf++) {
                    const uint32_t* bh = &bhi[nf >> 1][(nf & 1) * 2];
                    const uint32_t* bl = &blo[nf >> 1][(nf & 1) * 2];
                    mma_bf16(acc[mf][nf], ahi, bh);
                    mma_bf16(acc[mf][nf], ahi, bl);
                    mma_bf16(acc[mf][nf], alo, bh);
                }
            }
        }
    }
    __syncthreads();

    const int g  = lane >> 2;
    const int cc = (lane & 3) * 2;
    #pragma unroll
    for (int mf = 0; mf < 4; mf++)
        #pragma unroll
        for (int nf = 0; nf < 4; nf++) {
            const int mA = m0 + wm0 + mf * 16 + g;
            const int nA = n0 + wn0 + nf * 8 + cc;
            #pragma unroll
            for (int half = 0; half < 2; half++) {
                const int m = mA + half * 8;
                const float vx = acc[mf][nf][half * 2];
                const float vy = acc[mf][nf][half * 2 + 1];
                if (mode == 0) {
                    *(float2*)(C + (size_t)m * Dq + nA) = make_float2(vx, vy);
                } else {
                    const int bb = m >> 11;
                    const int ss = m & (Sq - 1);
                    const int hh = nA >> 6;
                    const int hd = nA & 63;
                    const size_t idx =
                        ((size_t)(bb * Hq + hh) * Sq + ss) * HDq + hd;
                    uint32_t ph, pl;
                    split2(vx * scale, vy * scale, ph, pl);
                    *(uint32_t*)(Chi + idx) = ph;
                    *(uint32_t*)(Clo + idx) = pl;
                }
            }
        }
}

__global__ __launch_bounds__(256, 2)
void gemm_mma_kernel(const __nv_bfloat16* __restrict__ Ahi,
                     const __nv_bfloat16* __restrict__ Alo,
                     const __nv_bfloat16* __restrict__ Bhi,
                     const __nv_bfloat16* __restrict__ Blo,
                     float* __restrict__ C)
{
    extern __shared__ __align__(16) char gsm[];
    gemm_body(gsm, Ahi, Alo, Bhi, Blo, C, nullptr, nullptr, 1.0f, 0);
}

__global__ __launch_bounds__(256, 2)
void gemm_qkv_kernel(const __nv_bfloat16* qhi, const __nv_bfloat16* qlo,
                     const __nv_bfloat16* khi, const __nv_bfloat16* klo,
                     const __nv_bfloat16* vhi, const __nv_bfloat16* vlo,
                     const __nv_bfloat16* wqhi, const __nv_bfloat16* wqlo,
                     const __nv_bfloat16* wkhi, const __nv_bfloat16* wklo,
                     const __nv_bfloat16* wvhi, const __nv_bfloat16* wvlo,
                     __nv_bfloat16* qhh, __nv_bfloat16* qhl,
                     __nv_bfloat16* khh, __nv_bfloat16* khl,
                     __nv_bfloat16* vhh, __nv_bfloat16* vhl)
{
    extern __shared__ __align__(16) char gsm[];
    const __nv_bfloat16 *Ah, *Al, *Bh, *Bl;
    __nv_bfloat16 *Ch, *Cl;
    float scale;
    switch (blockIdx.z) {
        case 0:  Ah=qhi; Al=qlo; Bh=wqhi; Bl=wqlo; Ch=qhh; Cl=qhl; scale=0.125f; break;
        case 1:  Ah=khi; Al=klo; Bh=wkhi; Bl=wklo; Ch=khh; Cl=khl; scale=1.0f;   break;
        default: Ah=vhi; Al=vlo; Bh=wvhi; Bl=wvlo; Ch=vhh; Cl=vhl; scale=1.0f;   break;
    }
    gemm_body(gsm, Ah, Al, Bh, Bl, nullptr, Ch, Cl, scale, 1);
}

// =====================================================================
// Tensor-core flash attention v3:
//  - 512 CTAs (one q-block each; round-11 structure that hit 288us)
//  - LPT scheduling: qb = 15 - blockIdx.x (heaviest CTAs launch first)
//  - 4-stage cp.async KV pipeline (prefetch distance 3)
//  - pad mask packed to 64 uint32 bit-words once per CTA
// Exact reference masking + conditional tail phase preserved.
// =====================================================================
#define AOFF_QLO 16384
#define AOFF_KV  32768
#define AKV_STG  32768
#define AOFF_KLO 8192
#define AOFF_VHI 16384
#define AOFF_VLO 24576
#define AOFF_PAD 163840
#define ATT_SMEM 172032

__global__ __launch_bounds__(256, 1)
void attn_kernel(const __nv_bfloat16* __restrict__ qhh, const __nv_bfloat16* __restrict__ qhl,
                 const __nv_bfloat16* __restrict__ khh, const __nv_bfloat16* __restrict__ khl,
                 const __nv_bfloat16* __restrict__ vhh, const __nv_bfloat16* __restrict__ vhl,
                 const int* __restrict__ attn_mask,
                 const int* __restrict__ mask_future_p,
                 __nv_bfloat16* __restrict__ chi, __nv_bfloat16* __restrict__ clo)
{
    extern __shared__ __align__(16) char smemb[];
    const uint32_t sb = smem_u32(smemb);
    __shared__ float wred[8];
    __shared__ int s_needtail;
    __shared__ uint32_t padbits[64];

    const int tid  = threadIdx.x;
    const int wid  = tid >> 5;
    const int lane = tid & 31;
    const int bh = blockIdx.y;            // b*H + h
    const int b  = bh >> 4;
    const int h  = bh & 15;
    const int qb = 15 - blockIdx.x;       // LPT: heaviest first
    const int qr0 = qb * 128;
    const int g  = lane >> 2;
    const int qd = lane & 3;
    const int mt = lane >> 3;
    const int rr = lane & 7;
    const int mask_future = mask_future_p[0];
    const int ntiles = Sq / 64;           // 32

    // group 1: pad mask
    #pragma unroll
    for (int k2 = 0; k2 < 2; k2++) {
        const int chunk = tid + k2 * 256;
        cpasync16(sb + AOFF_PAD + chunk * 16,
                  attn_mask + (size_t)b * Sq + chunk * 4);
    }
    CP_COMMIT();
    // group 2: Q tiles (hi+lo)
    #pragma unroll
    for (int j = 0; j < 8; j++) {
        const int idx = tid + j * 256;
        const int sel = idx >> 10;
        const int e = idx & 1023;
        const int r = e >> 3, c = e & 7;
        const __nv_bfloat16* src = (sel ? qhl : qhh) +
            ((size_t)bh * Sq + qr0 + r) * HDq + c * 8;
        cpasync16(sb + sel * 16384 + r * 128 + ((c ^ (r & 7)) << 4), src);
    }
    CP_COMMIT();
    bool padpacked = false;

    auto issue_kv = [&](int t, int s) {
        const int kv0 = t * 64;
        const uint32_t dst0 = sb + AOFF_KV + s * AKV_STG;
        #pragma unroll
        for (int j = 0; j < 8; j++) {
            const int idx = tid + j * 256;
            const int arr = idx >> 9;
            const int e = idx & 511;
            const int r = e >> 3, c = e & 7;
            const __nv_bfloat16* base =
                (arr == 0) ? khh : (arr == 1) ? khl : (arr == 2) ? vhh : vhl;
            const __nv_bfloat16* src = base + ((size_t)bh * Sq + kv0 + r) * HDq + c * 8;
            cpasync16(dst0 + arr * 8192 + r * 128 + ((c ^ (r & 7)) << 4), src);
        }
    };

    float m_[2] = {-1e30f, -1e30f};
    float l_[2] = {0.0f, 0.0f};
    float Of[8][4];
    #pragma unroll
    for (int j = 0; j < 8; j++)
        #pragma unroll
        for (int e = 0; e < 4; e++) Of[j][e] = 0.0f;
    uint32_t qfh[4][4], qfl[4][4];
    bool qloaded = false;

    const int limit = mask_future ? (2 * qb + 2) : ntiles;

    for (int phase = 0; phase < 2; phase++) {
        int t0, t1;
        if (phase == 0) { t0 = 0; t1 = limit; }
        else {
            if (!mask_future || limit >= ntiles) break;
            float mymin = fminf(m_[0], m_[1]);
            #pragma unroll
            for (int off = 16; off > 0; off >>= 1)
                mymin = fminf(mymin, __shfl_xor_sync(0xffffffffu, mymin, off));
            __syncthreads();
            if (lane == 0) wred[wid] = mymin;
            __syncthreads();
            if (tid == 0) {
                float mn = wred[0];
                #pragma unroll
                for (int w = 1; w < 8; w++) mn = fminf(mn, wred[w]);
                s_needtail = (mn < -5000.0f) ? 1 : 0;
            }
            __syncthreads();
            if (!s_needtail) break;
            t0 = limit; t1 = ntiles;
        }

        // prologue: 3 KV groups in flight
        #pragma unroll
        for (int pk = 0; pk < 3; pk++) {
            if (t0 + pk < t1) issue_kv(t0 + pk, pk);
            CP_COMMIT();
        }

        for (int i = t0; i < t1; i++) {
            CP_WAIT(2);
            __syncthreads();
            if (!padpacked) {
                if (tid < 64) {
                    const int* pz = (const int*)(smemb + AOFF_PAD) + tid * 32;
                    uint32_t w = 0;
                    #pragma unroll
                    for (int bb2 = 0; bb2 < 32; bb2++)
                        w |= (pz[bb2] ? 1u : 0u) << bb2;
                    padbits[tid] = w;
                }
                __syncthreads();
                padpacked = true;
            }
            if (!qloaded) {
                #pragma unroll
                for (int ks = 0; ks < 4; ks++) {
                    const int qrow = wid * 16 + rr + 8 * (mt & 1);
                    const int kch = 2 * ks + (mt >> 1);
                    const uint32_t ad = sb + qrow * 128 + ((kch ^ (qrow & 7)) << 4);
                    ldsm_x4(qfh[ks], ad);
                    ldsm_x4(qfl[ks], ad + AOFF_QLO);
                }
                qloaded = true;
            }
            if (i + 3 < t1) issue_kv(i + 3, (i - t0 + 3) & 3);
            CP_COMMIT();

            const uint32_t kb = sb + AOFF_KV + ((i - t0) & 3) * AKV_STG;
            const int kv0 = i * 64;

            // ---- S = Q K^T (hi/lo 3-pass) ----
            float cacc[8][4];
            #pragma unroll
            for (int j = 0; j < 8; j++)
                #pragma unroll
                for (int e = 0; e < 4; e++) cacc[j][e] = 0.0f;

            #pragma unroll
            for (int ks = 0; ks < 4; ks++) {
                #pragma unroll
                for (int np = 0; np < 4; np++) {
                    const int brow = np * 16 + rr + 8 * (mt >> 1);
                    const int kch = 2 * ks + (mt & 1);
                    const uint32_t ad = kb + brow * 128 + ((kch ^ (brow & 7)) << 4);
                    uint32_t k4h[4], k4l[4];
                    ldsm_x4(k4h, ad);
                    ldsm_x4(k4l, ad + AOFF_KLO);
                    mma_bf16(cacc[2*np],   qfh[ks], &k4h[0]);
                    mma_bf16(cacc[2*np],   qfh[ks], &k4l[0]);
                    mma_bf16(cacc[2*np],   qfl[ks], &k4h[0]);
                    mma_bf16(cacc[2*np+1], qfh[ks], &k4h[2]);
                    mma_bf16(cacc[2*np+1], qfh[ks], &k4l[2]);
                    mma_bf16(cacc[2*np+1], qfl[ks], &k4h[2]);
                }
            }

            // ---- mask (causal add then pad replace; bitmask words) ----
            const int row0 = qr0 + wid * 16 + g;
            const int row1 = row0 + 8;
            const uint32_t wA = padbits[2 * i];
            const uint32_t wB = padbits[2 * i + 1];
            #pragma unroll
            for (int j = 0; j < 8; j++) {
                const int cl = 8 * j + 2 * qd;           // 0..62, even
                const int col0 = kv0 + cl;
                float s0 = cacc[j][0], s1 = cacc[j][1];
                float s2 = cacc[j][2], s3 = cacc[j][3];
                if (mask_future) {
                    if (col0 > row0)     s0 += NEGV;
                    if (col0 + 1 > row0) s1 += NEGV;
                    if (col0 > row1)     s2 += NEGV;
                    if (col0 + 1 > row1) s3 += NEGV;
                }
                const uint32_t w = (cl & 32) ? wB : wA;
                const int sh = cl & 31;
                if (!((w >> sh) & 1u))       { s0 = NEGV; s2 = NEGV; }
                if (!((w >> (sh + 1)) & 1u)) { s1 = NEGV; s3 = NEGV; }
                cacc[j][0] = s0; cacc[j][1] = s1;
                cacc[j][2] = s2; cacc[j][3] = s3;
            }

            // ---- online softmax ----
            float mx0 = -1e30f, mx1 = -1e30f;
            #pragma unroll
            for (int j = 0; j < 8; j++) {
                mx0 = fmaxf(mx0, fmaxf(cacc[j][0], cacc[j][1]));
                mx1 = fmaxf(mx1, fmaxf(cacc[j][2], cacc[j][3]));
            }
            #pragma unroll
            for (int off = 1; off <= 2; off <<= 1) {
                mx0 = fmaxf(mx0, __shfl_xor_sync(0xffffffffu, mx0, off));
                mx1 = fmaxf(mx1, __shfl_xor_sync(0xffffffffu, mx1, off));
            }
            const float mn0 = fmaxf(m_[0], mx0);
            const float mn1 = fmaxf(m_[1], mx1);
            const float al0 = fexp_neg(m_[0] - mn0);
            const float al1 = fexp_neg(m_[1] - mn1);
            float rs0 = 0.0f, rs1 = 0.0f;
            #pragma unroll
            for (int j = 0; j < 8; j++) {
                const float p0 = fexp_neg(cacc[j][0] - mn0);
                const float p1 = fexp_neg(cacc[j][1] - mn0);
                const float p2 = fexp_neg(cacc[j][2] - mn1);
                const float p3 = fexp_neg(cacc[j][3] - mn1);
                cacc[j][0] = p0; cacc[j][1] = p1;
                cacc[j][2] = p2; cacc[j][3] = p3;
                rs0 += p0 + p1; rs1 += p2 + p3;
            }
            #pragma unroll
            for (int off = 1; off <= 2; off <<= 1) {
                rs0 += __shfl_xor_sync(0xffffffffu, rs0, off);
                rs1 += __shfl_xor_sync(0xffffffffu, rs1, off);
            }
            l_[0] = l_[0] * al0 + rs0;  m_[0] = mn0;
            l_[1] = l_[1] * al1 + rs1;  m_[1] = mn1;
            #pragma unroll
            for (int j = 0; j < 8; j++) {
                Of[j][0] *= al0; Of[j][1] *= al0;
                Of[j][2] *= al1; Of[j][3] *= al1;
            }

            // ---- O += P V (hi/lo 3-pass); P frag from S accumulator ----
            const uint32_t vb = kb + AOFF_VHI;
            #pragma unroll
            for (int ks = 0; ks < 4; ks++) {
                uint32_t pah[4], pal[4];
                split2(cacc[2*ks][0],   cacc[2*ks][1],   pah[0], pal[0]);
                split2(cacc[2*ks][2],   cacc[2*ks][3],   pah[1], pal[1]);
                split2(cacc[2*ks+1][0], cacc[2*ks+1][1], pah[2], pal[2]);
                split2(cacc[2*ks+1][2], cacc[2*ks+1][3], pah[3], pal[3]);
                #pragma unroll
                for (int np = 0; np < 4; np++) {
                    const int kvr = ks * 16 + rr + 8 * (mt & 1);
                    const int nch = 2 * np + (mt >> 1);
                    const uint32_t ad = vb + kvr * 128 + ((nch ^ (kvr & 7)) << 4);
                    uint32_t v4h[4], v4l[4];
                    ldsm_x4t(v4h, ad);
                    ldsm_x4t(v4l, ad + (AOFF_VLO - AOFF_VHI));
                    mma_bf16(Of[2*np],   pah, &v4h[0]);
                    mma_bf16(Of[2*np],   pah, &v4l[0]);
                    mma_bf16(Of[2*np],   pal, &v4h[0]);
                    mma_bf16(Of[2*np+1], pah, &v4h[2]);
                    mma_bf16(Of[2*np+1], pah, &v4l[2]);
                    mma_bf16(Of[2*np+1], pal, &v4h[2]);
                }
            }
        }
    }

    // ---- epilogue: normalize, write ctx hi/lo bf16 ----
    const float inv0 = 1.0f / l_[0];
    const float inv1 = 1.0f / l_[1];
    const int row0 = qr0 + wid * 16 + g;
    const int row1 = row0 + 8;
    #pragma unroll
    for (int jo = 0; jo < 8; jo++) {
        const int col = h * HDq + 8 * jo + 2 * qd;
        const size_t i0 = ((size_t)b * Sq + row0) * Dq + col;
        const size_t i1 = ((size_t)b * Sq + row1) * Dq + col;
        uint32_t ph, pl;
        split2(Of[jo][0] * inv0, Of[jo][1] * inv0, ph, pl);
        *(uint32_t*)(chi + i0) = ph;
        *(uint32_t*)(clo + i0) = pl;
        split2(Of[jo][2] * inv1, Of[jo][3] * inv1, ph, pl);
        *(uint32_t*)(chi + i1) = ph;
        *(uint32_t*)(clo + i1) = pl;
    }
}

// =====================================================================
// launch
// =====================================================================
extern "C" void kernel_launch(void* const* d_in, const int* in_sizes, int n_in,
                              void* d_out, int out_size)
{
    const float* q   = (const float*)d_in[0];
    const float* k   = (const float*)d_in[1];
    const float* v   = (const float*)d_in[2];
    const int*   am  = (const int*)  d_in[3];
    const float* Wq  = (const float*)d_in[4];
    const float* Wk  = (const float*)d_in[5];
    const float* Wv  = (const float*)d_in[6];
    const float* Wo  = (const float*)d_in[7];
    const int*   mf  = (const int*)  d_in[8];
    float* out = (float*)d_out;

    __nv_bfloat16 *qhi, *qlo, *khi, *klo, *vhi, *vlo;
    __nv_bfloat16 *wqhi, *wqlo, *wkhi, *wklo, *wvhi, *wvlo, *wohi, *wolo;
    __nv_bfloat16 *qhh, *qhl, *khh, *khl, *vhh, *vhl, *chi, *clo;
    cudaGetSymbolAddress((void**)&qhi,  g_q_hi);  cudaGetSymbolAddress((void**)&qlo,  g_q_lo);
    cudaGetSymbolAddress((void**)&khi,  g_k_hi);  cudaGetSymbolAddress((void**)&klo,  g_k_lo);
    cudaGetSymbolAddress((void**)&vhi,  g_v_hi);  cudaGetSymbolAddress((void**)&vlo,  g_v_lo);
    cudaGetSymbolAddress((void**)&wqhi, g_wq_hi); cudaGetSymbolAddress((void**)&wqlo, g_wq_lo);
    cudaGetSymbolAddress((void**)&wkhi, g_wk_hi); cudaGetSymbolAddress((void**)&wklo, g_wk_lo);
    cudaGetSymbolAddress((void**)&wvhi, g_wv_hi); cudaGetSymbolAddress((void**)&wvlo, g_wv_lo);
    cudaGetSymbolAddress((void**)&wohi, g_wo_hi); cudaGetSymbolAddress((void**)&wolo, g_wo_lo);
    cudaGetSymbolAddress((void**)&qhh,  g_qhh);   cudaGetSymbolAddress((void**)&qhl,  g_qhl);
    cudaGetSymbolAddress((void**)&khh,  g_khh);   cudaGetSymbolAddress((void**)&khl,  g_khl);
    cudaGetSymbolAddress((void**)&vhh,  g_vhh);   cudaGetSymbolAddress((void**)&vhl,  g_vhl);
    cudaGetSymbolAddress((void**)&chi,  g_c_hi);  cudaGetSymbolAddress((void**)&clo,  g_c_lo);

    cudaFuncSetAttribute(gemm_mma_kernel,
                         cudaFuncAttributeMaxDynamicSharedMemorySize, GEMM_SMEM);
    cudaFuncSetAttribute(gemm_qkv_kernel,
                         cudaFuncAttributeMaxDynamicSharedMemorySize, GEMM_SMEM);
    cudaFuncSetAttribute(attn_kernel,
                         cudaFuncAttributeMaxDynamicSharedMemorySize, ATT_SMEM);

    // 1) hi/lo conversions
    const int nIn4 = Mq * Dq / 4;
    const int nW4  = Dq * Dq / 4;
    {
        dim3 g3(nIn4 / 256, 1, 3);
        cvt_hilo3_kernel<<<g3, 256>>>(q, k, v, qhi, qlo, khi, klo, vhi, vlo, nIn4);
        dim3 g4(nW4 / 256, 1, 4);
        cvt_hilo4_kernel<<<g4, 256>>>(Wq, Wk, Wv, Wo,
                                      wqhi, wqlo, wkhi, wklo,
                                      wvhi, wvlo, wohi, wolo, nW4);
    }

    // 2) fused QKV projections -> bf16 hi/lo head-split (Q pre-scaled 1/8)
    dim3 qkv_grid(Dq / 128, Mq / 128, 3);
    gemm_qkv_kernel<<<qkv_grid, 256, GEMM_SMEM>>>(
        qhi, qlo, khi, klo, vhi, vlo,
        wqhi, wqlo, wkhi, wklo, wvhi, wvlo,
        qhh, qhl, khh, khl, vhh, vhl);

    // 3) tensor-core flash attention (512 CTAs, LPT) -> ctx hi/lo bf16
    dim3 attn_grid(Sq / 128, Bq * Hq);   // (16, 32) = 512 CTAs
    attn_kernel<<<attn_grid, 256, ATT_SMEM>>>(
        qhh, qhl, khh, khl, vhh, vhl, am, mf, chi, clo);

    // 4) output projection
    dim3 gemm_grid(Dq / 128, Mq / 128);
    gemm_mma_kernel<<<gemm_grid, 256, GEMM_SMEM>>>(chi, clo, wohi, wolo, out);
}

// round 15
// speedup vs baseline: 1.1890x; 1.0864x over previous
#include <cuda_runtime.h>
#include <cuda_bf16.h>
#include <math.h>
#include <stdint.h>

// ---------------- problem constants ----------------
#define Bq   2
#define Sq   2048
#define Dq   1024
#define Hq   16
#define HDq  64
#define Mq   (Bq*Sq)          // 4096
#define NEGV (-10000.0f)

// ---------------- scratch (device globals; no allocation allowed) ----------
__device__ __nv_bfloat16 g_q_hi[Mq*Dq],  g_q_lo[Mq*Dq];
__device__ __nv_bfloat16 g_k_hi[Mq*Dq],  g_k_lo[Mq*Dq];
__device__ __nv_bfloat16 g_v_hi[Mq*Dq],  g_v_lo[Mq*Dq];
__device__ __nv_bfloat16 g_wq_hi[Dq*Dq], g_wq_lo[Dq*Dq];
__device__ __nv_bfloat16 g_wk_hi[Dq*Dq], g_wk_lo[Dq*Dq];
__device__ __nv_bfloat16 g_wv_hi[Dq*Dq], g_wv_lo[Dq*Dq];
__device__ __nv_bfloat16 g_wo_hi[Dq*Dq], g_wo_lo[Dq*Dq];
__device__ __nv_bfloat16 g_qhh[Bq*Hq*Sq*HDq], g_qhl[Bq*Hq*Sq*HDq];
__device__ __nv_bfloat16 g_khh[Bq*Hq*Sq*HDq], g_khl[Bq*Hq*Sq*HDq];
__device__ __nv_bfloat16 g_vhh[Bq*Hq*Sq*HDq], g_vhl[Bq*Hq*Sq*HDq];
__device__ __nv_bfloat16 g_c_hi[Mq*Dq], g_c_lo[Mq*Dq];

// =====================================================================
// helpers
// =====================================================================
__device__ __forceinline__ uint32_t smem_u32(const void* p) {
    uint32_t a;
    asm("{ .reg .u64 t; cvta.to.shared.u64 t, %1; cvt.u32.u64 %0, t; }"
        : "=r"(a) : "l"(p));
    return a;
}

__device__ __forceinline__ void ldsm_x4(uint32_t* r, uint32_t addr) {
    asm volatile("ldmatrix.sync.aligned.m8n8.x4.shared.b16 {%0,%1,%2,%3}, [%4];"
                 : "=r"(r[0]), "=r"(r[1]), "=r"(r[2]), "=r"(r[3]) : "r"(addr));
}
__device__ __forceinline__ void ldsm_x4t(uint32_t* r, uint32_t addr) {
    asm volatile("ldmatrix.sync.aligned.m8n8.x4.trans.shared.b16 {%0,%1,%2,%3}, [%4];"
                 : "=r"(r[0]), "=r"(r[1]), "=r"(r[2]), "=r"(r[3]) : "r"(addr));
}

__device__ __forceinline__ void mma_bf16(float* c, const uint32_t* a,
                                         const uint32_t* b) {
    asm volatile(
        "mma.sync.aligned.m16n8k16.row.col.f32.bf16.bf16.f32 "
        "{%0,%1,%2,%3}, {%4,%5,%6,%7}, {%8,%9}, {%0,%1,%2,%3};"
        : "+f"(c[0]), "+f"(c[1]), "+f"(c[2]), "+f"(c[3])
        : "r"(a[0]), "r"(a[1]), "r"(a[2]), "r"(a[3]), "r"(b[0]), "r"(b[1]));
}

__device__ __forceinline__ void cpasync16(uint32_t dst, const void* src) {
    asm volatile("cp.async.cg.shared.global [%0], [%1], 16;"
                 :: "r"(dst), "l"(src) : "memory");
}
#define CP_COMMIT() asm volatile("cp.async.commit_group;" ::: "memory")
#define CP_WAIT(n)  asm volatile("cp.async.wait_group %0;" :: "n"(n) : "memory")

// Fast exp for x <= 0 on FMA/ALU pipes only (validated rounds 10-14).
__device__ __forceinline__ float fexp_neg(float x) {
    x = fmaxf(x, -80.0f);
    const float y = x * 1.4426950408889634f;
    const float t = y + 12582912.0f;
    const float nf = t - 12582912.0f;
    const float f = y - nf;
    const uint32_t sbits = (__float_as_uint(t) + (127u - 0x400000u)) << 23;
    float p = 0.0013333558f;
    p = fmaf(p, f, 0.0096181291f);
    p = fmaf(p, f, 0.0555041087f);
    p = fmaf(p, f, 0.2402265069f);
    p = fmaf(p, f, 0.6931471806f);
    p = fmaf(p, f, 1.0f);
    return p * __uint_as_float(sbits);
}

__device__ __forceinline__ void split2(float x, float y, uint32_t& hi, uint32_t& lo) {
    __nv_bfloat16 hx = __float2bfloat16(x), hy = __float2bfloat16(y);
    hi = (uint32_t)__bfloat16_as_ushort(hx) |
         ((uint32_t)__bfloat16_as_ushort(hy) << 16);
    __nv_bfloat16 lx = __float2bfloat16(x - __bfloat162float(hx));
    __nv_bfloat16 ly = __float2bfloat16(y - __bfloat162float(hy));
    lo = (uint32_t)__bfloat16_as_ushort(lx) |
         ((uint32_t)__bfloat16_as_ushort(ly) << 16);
}

// =====================================================================
// fp32 -> bf16 hi/lo split
// =====================================================================
__device__ __forceinline__ void cvt_body(const float* __restrict__ x,
                                         __nv_bfloat16* __restrict__ hi,
                                         __nv_bfloat16* __restrict__ lo,
                                         int n4)
{
    int i = blockIdx.x * blockDim.x + threadIdx.x;
    if (i >= n4) return;
    float4 v = ((const float4*)x)[i];
    uint32_t h0, l0, h1, l1;
    split2(v.x, v.y, h0, l0);
    split2(v.z, v.w, h1, l1);
    ((uint2*)hi)[i] = make_uint2(h0, h1);
    ((uint2*)lo)[i] = make_uint2(l0, l1);
}

__global__ __launch_bounds__(256)
void cvt_hilo3_kernel(const float* x0, const float* x1, const float* x2,
                      __nv_bfloat16* h0, __nv_bfloat16* l0,
                      __nv_bfloat16* h1, __nv_bfloat16* l1,
                      __nv_bfloat16* h2, __nv_bfloat16* l2, int n4)
{
    const float* x; __nv_bfloat16 *hh, *ll;
    switch (blockIdx.z) {
        case 0:  x = x0; hh = h0; ll = l0; break;
        case 1:  x = x1; hh = h1; ll = l1; break;
        default: x = x2; hh = h2; ll = l2; break;
    }
    cvt_body(x, hh, ll, n4);
}

__global__ __launch_bounds__(256)
void cvt_hilo4_kernel(const float* x0, const float* x1, const float* x2, const float* x3,
                      __nv_bfloat16* h0, __nv_bfloat16* l0,
                      __nv_bfloat16* h1, __nv_bfloat16* l1,
                      __nv_bfloat16* h2, __nv_bfloat16* l2,
                      __nv_bfloat16* h3, __nv_bfloat16* l3, int n4)
{
    const float* x; __nv_bfloat16 *hh, *ll;
    switch (blockIdx.z) {
        case 0:  x = x0; hh = h0; ll = l0; break;
        case 1:  x = x1; hh = h1; ll = l1; break;
        case 2:  x = x2; hh = h2; ll = l2; break;
        default: x = x3; hh = h3; ll = l3; break;
    }
    cvt_body(x, hh, ll, n4);
}

// =====================================================================
// Tensor-core GEMM (validated rounds 9-14; unchanged):
// =====================================================================
#define GSTG 32768
#define GOFF_ALO 8192
#define GOFF_BHI 16384
#define GOFF_BLO 24576
#define GEMM_SMEM (3*GSTG)

__device__ __forceinline__
void gemm_body(char* gsm,
               const __nv_bfloat16* __restrict__ Ahi,
               const __nv_bfloat16* __restrict__ Alo,
               const __nv_bfloat16* __restrict__ Bhi,
               const __nv_bfloat16* __restrict__ Blo,
               float* __restrict__ C,
               __nv_bfloat16* __restrict__ Chi,
               __nv_bfloat16* __restrict__ Clo,
               float scale, int mode)
{
    const uint32_t sbase = smem_u32(gsm);

    const int tid  = threadIdx.x;
    const int wid  = tid >> 5;
    const int lane = tid & 31;
    const int m0 = blockIdx.y * 128;
    const int n0 = blockIdx.x * 128;
    const int wm0 = (wid & 1) * 64;
    const int wn0 = (wid >> 1) * 32;

    const int mt = lane >> 3;
    const int rr = lane & 7;
    const int a_row = rr + 8 * (mt & 1);
    const int a_kof = 8 * (mt >> 1);
    const int b_row = rr + 8 * (mt >> 1);
    const int b_kof = 8 * (mt & 1);

    const int ld_r0 = tid >> 2;
    const int ld_c0 = tid & 3;
    const int ld_r1 = ld_r0 + 64;

    float acc[4][4][4];
    #pragma unroll
    for (int i = 0; i < 4; i++)
        #pragma unroll
        for (int j = 0; j < 4; j++)
            #pragma unroll
            for (int e = 0; e < 4; e++) acc[i][j][e] = 0.0f;

    auto issue_stage = [&](int ch, int stg) {
        const int k0 = ch * 32;
        const uint32_t sst = sbase + stg * GSTG;
        {
            const int r = ld_r0, c = ld_c0;
            const uint32_t sw = (uint32_t)(r * 64 + ((c ^ ((r >> 1) & 3)) << 4));
            const size_t goA = (size_t)(m0 + r) * Dq + k0 + c * 8;
            const size_t goB = (size_t)(n0 + r) * Dq + k0 + c * 8;
            cpasync16(sst + sw,            Ahi + goA);
            cpasync16(sst + GOFF_ALO + sw, Alo + goA);
            cpasync16(sst + GOFF_BHI + sw, Bhi + goB);
            cpasync16(sst + GOFF_BLO + sw, Blo + goB);
        }
        {
            const int r = ld_r1, c = ld_c0;
            const uint32_t sw = (uint32_t)(r * 64 + ((c ^ ((r >> 1) & 3)) << 4));
            const size_t goA = (size_t)(m0 + r) * Dq + k0 + c * 8;
            const size_t goB = (size_t)(n0 + r) * Dq + k0 + c * 8;
            cpasync16(sst + sw,            Ahi + goA);
            cpasync16(sst + GOFF_ALO + sw, Alo + goA);
            cpasync16(sst + GOFF_BHI + sw, Bhi + goB);
            cpasync16(sst + GOFF_BLO + sw, Blo + goB);
        }
    };

    issue_stage(0, 0); CP_COMMIT();
    issue_stage(1, 1); CP_COMMIT();

    const int NCH = Dq / 32;   // 32
    for (int ch = 0; ch < NCH; ch++) {
        CP_WAIT(1);
        __syncthreads();
        if (ch + 2 < NCH) issue_stage(ch + 2, (ch + 2) % 3);
        CP_COMMIT();

        const uint32_t sst = sbase + (ch % 3) * GSTG;
        #pragma unroll
        for (int ks = 0; ks < 32; ks += 16) {
            uint32_t bhi[2][4], blo[2][4];
            #pragma unroll
            for (int p = 0; p < 2; p++) {
                const int row = wn0 + p * 16 + b_row;
                const int cch = (ks + b_kof) >> 3;
                const uint32_t ad = sst + GOFF_BHI +
                    (uint32_t)(row * 64 + ((cch ^ ((row >> 1) & 3)) << 4));
                ldsm_x4(bhi[p], ad);
                ldsm_x4(blo[p], ad + (GOFF_BLO - GOFF_BHI));
            }
            #pragma unroll
            for (int mf = 0; mf < 4; mf++) {
                const int row = wm0 + mf * 16 + a_row;
                const int cch = (ks + a_kof) >> 3;
                const uint32_t ad = sst +
                    (uint32_t)(row * 64 + ((cch ^ ((row >> 1) & 3)) << 4));
                uint32_t ahi[4], alo[4];
                ldsm_x4(ahi, ad);
                ldsm_x4(alo, ad + GOFF_ALO);
                #pragma unroll
                for (int nf = 0; nf < 4; nf++) {
                    const uint32_t* bh = &bhi[nf >> 1][(nf & 1) * 2];
                    const uint32_t* bl = &blo[nf >> 1][(nf & 1) * 2];
                    mma_bf16(acc[mf][nf], ahi, bh);
                    mma_bf16(acc[mf][nf], ahi, bl);
                    mma_bf16(acc[mf][nf], alo, bh);
                }
            }
        }
    }
    __syncthreads();

    const int g  = lane >> 2;
    const int cc = (lane & 3) * 2;
    #pragma unroll
    for (int mf = 0; mf < 4; mf++)
        #pragma unroll
        for (int nf = 0; nf < 4; nf++) {
            const int mA = m0 + wm0 + mf * 16 + g;
            const int nA = n0 + wn0 + nf * 8 + cc;
            #pragma unroll
            for (int half = 0; half < 2; half++) {
                const int m = mA + half * 8;
                const float vx = acc[mf][nf][half * 2];
                const float vy = acc[mf][nf][half * 2 + 1];
                if (mode == 0) {
                    *(float2*)(C + (size_t)m * Dq + nA) = make_float2(vx, vy);
                } else {
                    const int bb = m >> 11;
                    const int ss = m & (Sq - 1);
                    const int hh = nA >> 6;
                    const int hd = nA & 63;
                    const size_t idx =
                        ((size_t)(bb * Hq + hh) * Sq + ss) * HDq + hd;
                    uint32_t ph, pl;
                    split2(vx * scale, vy * scale, ph, pl);
                    *(uint32_t*)(Chi + idx) = ph;
                    *(uint32_t*)(Clo + idx) = pl;
                }
            }
        }
}

__global__ __launch_bounds__(256, 2)
void gemm_mma_kernel(const __nv_bfloat16* __restrict__ Ahi,
                     const __nv_bfloat16* __restrict__ Alo,
                     const __nv_bfloat16* __restrict__ Bhi,
                     const __nv_bfloat16* __restrict__ Blo,
                     float* __restrict__ C)
{
    extern __shared__ __align__(16) char gsm[];
    gemm_body(gsm, Ahi, Alo, Bhi, Blo, C, nullptr, nullptr, 1.0f, 0);
}

__global__ __launch_bounds__(256, 2)
void gemm_qkv_kernel(const __nv_bfloat16* qhi, const __nv_bfloat16* qlo,
                     const __nv_bfloat16* khi, const __nv_bfloat16* klo,
                     const __nv_bfloat16* vhi, const __nv_bfloat16* vlo,
                     const __nv_bfloat16* wqhi, const __nv_bfloat16* wqlo,
                     const __nv_bfloat16* wkhi, const __nv_bfloat16* wklo,
                     const __nv_bfloat16* wvhi, const __nv_bfloat16* wvlo,
                     __nv_bfloat16* qhh, __nv_bfloat16* qhl,
                     __nv_bfloat16* khh, __nv_bfloat16* khl,
                     __nv_bfloat16* vhh, __nv_bfloat16* vhl)
{
    extern __shared__ __align__(16) char gsm[];
    const __nv_bfloat16 *Ah, *Al, *Bh, *Bl;
    __nv_bfloat16 *Ch, *Cl;
    float scale;
    switch (blockIdx.z) {
        case 0:  Ah=qhi; Al=qlo; Bh=wqhi; Bl=wqlo; Ch=qhh; Cl=qhl; scale=0.125f; break;
        case 1:  Ah=khi; Al=klo; Bh=wkhi; Bl=wklo; Ch=khh; Cl=khl; scale=1.0f;   break;
        default: Ah=vhi; Al=vlo; Bh=wvhi; Bl=wvlo; Ch=vhh; Cl=vhl; scale=1.0f;   break;
    }
    gemm_body(gsm, Ah, Al, Bh, Bl, nullptr, Ch, Cl, scale, 1);
}

// =====================================================================
// Tensor-core flash attention v4:
//  - 4-warp CTAs, 64 Q rows each -> 90KB smem, <=256 regs -> 2 CTAs/SM
//    (doubles warp contexts per SMSP: 2 -> 4, hides mma/fexp latency)
//  - 2-stage cp.async KV pipeline (per-tile compute >> load latency)
//  - 1024 CTAs, LPT order (qb = 31 - blockIdx.x)
//  - pad mask packed to 64 uint32 bit-words once per CTA
// Exact reference masking + conditional tail phase preserved.
// =====================================================================
#define AOFF_QLO 8192
#define AOFF_KV  16384
#define AKV_STG  32768
#define AOFF_KLO 8192
#define AOFF_VHI 16384
#define AOFF_VLO 24576
#define AOFF_PAD 81920
#define ATT_SMEM 90112

__global__ __launch_bounds__(128, 2)
void attn_kernel(const __nv_bfloat16* __restrict__ qhh, const __nv_bfloat16* __restrict__ qhl,
                 const __nv_bfloat16* __restrict__ khh, const __nv_bfloat16* __restrict__ khl,
                 const __nv_bfloat16* __restrict__ vhh, const __nv_bfloat16* __restrict__ vhl,
                 const int* __restrict__ attn_mask,
                 const int* __restrict__ mask_future_p,
                 __nv_bfloat16* __restrict__ chi, __nv_bfloat16* __restrict__ clo)
{
    extern __shared__ __align__(16) char smemb[];
    const uint32_t sb = smem_u32(smemb);
    __shared__ float wred[4];
    __shared__ int s_needtail;
    __shared__ uint32_t padbits[64];

    const int tid  = threadIdx.x;
    const int wid  = tid >> 5;            // 0..3 : one m16 tile each
    const int lane = tid & 31;
    const int bh = blockIdx.y;            // b*H + h
    const int b  = bh >> 4;
    const int h  = bh & 15;
    const int qb = 31 - blockIdx.x;       // LPT: heaviest first (64-row blocks)
    const int qr0 = qb * 64;
    const int g  = lane >> 2;
    const int qd = lane & 3;
    const int mt = lane >> 3;
    const int rr = lane & 7;
    const int mask_future = mask_future_p[0];
    const int ntiles = Sq / 64;           // 32

    // group 1: pad mask (2048 ints = 512 chunks; 4 per thread)
    #pragma unroll
    for (int k2 = 0; k2 < 4; k2++) {
        const int chunk = tid + k2 * 128;
        cpasync16(sb + AOFF_PAD + chunk * 16,
                  attn_mask + (size_t)b * Sq + chunk * 4);
    }
    CP_COMMIT();
    // group 2: Q tiles hi+lo (64 rows x 8 chunks x 2 = 1024 chunks; 8/thread)
    #pragma unroll
    for (int j = 0; j < 8; j++) {
        const int idx = tid + j * 128;
        const int sel = idx >> 9;              // 0 hi / 1 lo (512 chunks each)
        const int e = idx & 511;
        const int r = e >> 3, c = e & 7;
        const __nv_bfloat16* src = (sel ? qhl : qhh) +
            ((size_t)bh * Sq + qr0 + r) * HDq + c * 8;
        cpasync16(sb + sel * AOFF_QLO + r * 128 + ((c ^ (r & 7)) << 4), src);
    }
    CP_COMMIT();
    bool padpacked = false;

    auto issue_kv = [&](int t, int s) {
        const int kv0 = t * 64;
        const uint32_t dst0 = sb + AOFF_KV + s * AKV_STG;
        #pragma unroll
        for (int j = 0; j < 16; j++) {
            const int idx = tid + j * 128;         // 0..2047
            const int arr = idx >> 9;              // 0 khi,1 klo,2 vhi,3 vlo
            const int e = idx & 511;
            const int r = e >> 3, c = e & 7;
            const __nv_bfloat16* base =
                (arr == 0) ? khh : (arr == 1) ? khl : (arr == 2) ? vhh : vhl;
            const __nv_bfloat16* src = base + ((size_t)bh * Sq + kv0 + r) * HDq + c * 8;
            cpasync16(dst0 + arr * 8192 + r * 128 + ((c ^ (r & 7)) << 4), src);
        }
    };

    float m_[2] = {-1e30f, -1e30f};
    float l_[2] = {0.0f, 0.0f};
    float Of[8][4];
    #pragma unroll
    for (int j = 0; j < 8; j++)
        #pragma unroll
        for (int e = 0; e < 4; e++) Of[j][e] = 0.0f;
    uint32_t qfh[4][4], qfl[4][4];
    bool qloaded = false;

    const int limit = mask_future ? (qb + 1) : ntiles;

    for (int phase = 0; phase < 2; phase++) {
        int t0, t1;
        if (phase == 0) { t0 = 0; t1 = limit; }
        else {
            if (!mask_future || limit >= ntiles) break;
            float mymin = fminf(m_[0], m_[1]);
            #pragma unroll
            for (int off = 16; off > 0; off >>= 1)
                mymin = fminf(mymin, __shfl_xor_sync(0xffffffffu, mymin, off));
            __syncthreads();
            if (lane == 0) wred[wid] = mymin;
            __syncthreads();
            if (tid == 0) {
                float mn = fminf(fminf(wred[0], wred[1]), fminf(wred[2], wred[3]));
                s_needtail = (mn < -5000.0f) ? 1 : 0;
            }
            __syncthreads();
            if (!s_needtail) break;
            t0 = limit; t1 = ntiles;
        }

        // prologue: 2 KV stages in flight
        issue_kv(t0, 0); CP_COMMIT();
        if (t0 + 1 < t1) issue_kv(t0 + 1, 1);
        CP_COMMIT();

        for (int i = t0; i < t1; i++) {
            CP_WAIT(1);          // stage i complete (pad+Q complete by 1st iter)
            __syncthreads();
            if (!padpacked) {
                if (tid < 64) {
                    const int* pz = (const int*)(smemb + AOFF_PAD) + tid * 32;
                    uint32_t w = 0;
                    #pragma unroll
                    for (int bb2 = 0; bb2 < 32; bb2++)
                        w |= (pz[bb2] ? 1u : 0u) << bb2;
                    padbits[tid] = w;
                }
                __syncthreads();
                padpacked = true;
            }
            if (!qloaded) {
                #pragma unroll
                for (int ks = 0; ks < 4; ks++) {
                    const int qrow = wid * 16 + rr + 8 * (mt & 1);
                    const int kch = 2 * ks + (mt >> 1);
                    const uint32_t ad = sb + qrow * 128 + ((kch ^ (qrow & 7)) << 4);
                    ldsm_x4(qfh[ks], ad);
                    ldsm_x4(qfl[ks], ad + AOFF_QLO);
                }
                qloaded = true;
            }

            const uint32_t kb = sb + AOFF_KV + ((i - t0) & 1) * AKV_STG;
            const int kv0 = i * 64;

            // ---- S = Q K^T (hi/lo 3-pass) ----
            float cacc[8][4];
            #pragma unroll
            for (int j = 0; j < 8; j++)
                #pragma unroll
                for (int e = 0; e < 4; e++) cacc[j][e] = 0.0f;

            #pragma unroll
            for (int ks = 0; ks < 4; ks++) {
                #pragma unroll
                for (int np = 0; np < 4; np++) {
                    const int brow = np * 16 + rr + 8 * (mt >> 1);
                    const int kch = 2 * ks + (mt & 1);
                    const uint32_t ad = kb + brow * 128 + ((kch ^ (brow & 7)) << 4);
                    uint32_t k4h[4], k4l[4];
                    ldsm_x4(k4h, ad);
                    ldsm_x4(k4l, ad + AOFF_KLO);
                    mma_bf16(cacc[2*np],   qfh[ks], &k4h[0]);
                    mma_bf16(cacc[2*np],   qfh[ks], &k4l[0]);
                    mma_bf16(cacc[2*np],   qfl[ks], &k4h[0]);
                    mma_bf16(cacc[2*np+1], qfh[ks], &k4h[2]);
                    mma_bf16(cacc[2*np+1], qfh[ks], &k4l[2]);
                    mma_bf16(cacc[2*np+1], qfl[ks], &k4h[2]);
                }
            }

            // ---- mask (causal add then pad replace; bitmask words) ----
            const int row0 = qr0 + wid * 16 + g;
            const int row1 = row0 + 8;
            const uint32_t wA = padbits[2 * i];
            const uint32_t wB = padbits[2 * i + 1];
            #pragma unroll
            for (int j = 0; j < 8; j++) {
                const int cl = 8 * j + 2 * qd;           // 0..62, even
                const int col0 = kv0 + cl;
                float s0 = cacc[j][0], s1 = cacc[j][1];
                float s2 = cacc[j][2], s3 = cacc[j][3];
                if (mask_future) {
                    if (col0 > row0)     s0 += NEGV;
                    if (col0 + 1 > row0) s1 += NEGV;
                    if (col0 > row1)     s2 += NEGV;
                    if (col0 + 1 > row1) s3 += NEGV;
                }
                const uint32_t w = (cl & 32) ? wB : wA;
                const int sh = cl & 31;
                if (!((w >> sh) & 1u))       { s0 = NEGV; s2 = NEGV; }
                if (!((w >> (sh + 1)) & 1u)) { s1 = NEGV; s3 = NEGV; }
                cacc[j][0] = s0; cacc[j][1] = s1;
                cacc[j][2] = s2; cacc[j][3] = s3;
            }

            // ---- online softmax ----
            float mx0 = -1e30f, mx1 = -1e30f;
            #pragma unroll
            for (int j = 0; j < 8; j++) {
                mx0 = fmaxf(mx0, fmaxf(cacc[j][0], cacc[j][1]));
                mx1 = fmaxf(mx1, fmaxf(cacc[j][2], cacc[j][3]));
            }
            #pragma unroll
            for (int off = 1; off <= 2; off <<= 1) {
                mx0 = fmaxf(mx0, __shfl_xor_sync(0xffffffffu, mx0, off));
                mx1 = fmaxf(mx1, __shfl_xor_sync(0xffffffffu, mx1, off));
            }
            const float mn0 = fmaxf(m_[0], mx0);
            const float mn1 = fmaxf(m_[1], mx1);
            const float al0 = fexp_neg(m_[0] - mn0);
            const float al1 = fexp_neg(m_[1] - mn1);
            float rs0 = 0.0f, rs1 = 0.0f;
            #pragma unroll
            for (int j = 0; j < 8; j++) {
                const float p0 = fexp_neg(cacc[j][0] - mn0);
                const float p1 = fexp_neg(cacc[j][1] - mn0);
                const float p2 = fexp_neg(cacc[j][2] - mn1);
                const float p3 = fexp_neg(cacc[j][3] - mn1);
                cacc[j][0] = p0; cacc[j][1] = p1;
                cacc[j][2] = p2; cacc[j][3] = p3;
                rs0 += p0 + p1; rs1 += p2 + p3;
            }
            #pragma unroll
            for (int off = 1; off <= 2; off <<= 1) {
                rs0 += __shfl_xor_sync(0xffffffffu, rs0, off);
                rs1 += __shfl_xor_sync(0xffffffffu, rs1, off);
            }
            l_[0] = l_[0] * al0 + rs0;  m_[0] = mn0;
            l_[1] = l_[1] * al1 + rs1;  m_[1] = mn1;
            #pragma unroll
            for (int j = 0; j < 8; j++) {
                Of[j][0] *= al0; Of[j][1] *= al0;
                Of[j][2] *= al1; Of[j][3] *= al1;
            }

            // ---- O += P V (hi/lo 3-pass); P frag from S accumulator ----
            const uint32_t vb = kb + AOFF_VHI;
            #pragma unroll
            for (int ks = 0; ks < 4; ks++) {
                uint32_t pah[4], pal[4];
                split2(cacc[2*ks][0],   cacc[2*ks][1],   pah[0], pal[0]);
                split2(cacc[2*ks][2],   cacc[2*ks][3],   pah[1], pal[1]);
                split2(cacc[2*ks+1][0], cacc[2*ks+1][1], pah[2], pal[2]);
                split2(cacc[2*ks+1][2], cacc[2*ks+1][3], pah[3], pal[3]);
                #pragma unroll
                for (int np = 0; np < 4; np++) {
                    const int kvr = ks * 16 + rr + 8 * (mt & 1);
                    const int nch = 2 * np + (mt >> 1);
                    const uint32_t ad = vb + kvr * 128 + ((nch ^ (kvr & 7)) << 4);
                    uint32_t v4h[4], v4l[4];
                    ldsm_x4t(v4h, ad);
                    ldsm_x4t(v4l, ad + (AOFF_VLO - AOFF_VHI));
                    mma_bf16(Of[2*np],   pah, &v4h[0]);
                    mma_bf16(Of[2*np],   pah, &v4l[0]);
                    mma_bf16(Of[2*np],   pal, &v4h[0]);
                    mma_bf16(Of[2*np+1], pah, &v4h[2]);
                    mma_bf16(Of[2*np+1], pah, &v4l[2]);
                    mma_bf16(Of[2*np+1], pal, &v4h[2]);
                }
            }

            // all warps done reading this stage; refill it for tile i+2
            __syncthreads();
            if (i + 2 < t1) issue_kv(i + 2, (i - t0) & 1);
            CP_COMMIT();
        }
    }

    // ---- epilogue: normalize, write ctx hi/lo bf16 ----
    const float inv0 = 1.0f / l_[0];
    const float inv1 = 1.0f / l_[1];
    const int row0 = qr0 + wid * 16 + g;
    const int row1 = row0 + 8;
    #pragma unroll
    for (int jo = 0; jo < 8; jo++) {
        const int col = h * HDq + 8 * jo + 2 * qd;
        const size_t i0 = ((size_t)b * Sq + row0) * Dq + col;
        const size_t i1 = ((size_t)b * Sq + row1) * Dq + col;
        uint32_t ph, pl;
        split2(Of[jo][0] * inv0, Of[jo][1] * inv0, ph, pl);
        *(uint32_t*)(chi + i0) = ph;
        *(uint32_t*)(clo + i0) = pl;
        split2(Of[jo][2] * inv1, Of[jo][3] * inv1, ph, pl);
        *(uint32_t*)(chi + i1) = ph;
        *(uint32_t*)(clo + i1) = pl;
    }
}

// =====================================================================
// launch
// =====================================================================
extern "C" void kernel_launch(void* const* d_in, const int* in_sizes, int n_in,
                              void* d_out, int out_size)
{
    const float* q   = (const float*)d_in[0];
    const float* k   = (const float*)d_in[1];
    const float* v   = (const float*)d_in[2];
    const int*   am  = (const int*)  d_in[3];
    const float* Wq  = (const float*)d_in[4];
    const float* Wk  = (const float*)d_in[5];
    const float* Wv  = (const float*)d_in[6];
    const float* Wo  = (const float*)d_in[7];
    const int*   mf  = (const int*)  d_in[8];
    float* out = (float*)d_out;

    __nv_bfloat16 *qhi, *qlo, *khi, *klo, *vhi, *vlo;
    __nv_bfloat16 *wqhi, *wqlo, *wkhi, *wklo, *wvhi, *wvlo, *wohi, *wolo;
    __nv_bfloat16 *qhh, *qhl, *khh, *khl, *vhh, *vhl, *chi, *clo;
    cudaGetSymbolAddress((void**)&qhi,  g_q_hi);  cudaGetSymbolAddress((void**)&qlo,  g_q_lo);
    cudaGetSymbolAddress((void**)&khi,  g_k_hi);  cudaGetSymbolAddress((void**)&klo,  g_k_lo);
    cudaGetSymbolAddress((void**)&vhi,  g_v_hi);  cudaGetSymbolAddress((void**)&vlo,  g_v_lo);
    cudaGetSymbolAddress((void**)&wqhi, g_wq_hi); cudaGetSymbolAddress((void**)&wqlo, g_wq_lo);
    cudaGetSymbolAddress((void**)&wkhi, g_wk_hi); cudaGetSymbolAddress((void**)&wklo, g_wk_lo);
    cudaGetSymbolAddress((void**)&wvhi, g_wv_hi); cudaGetSymbolAddress((void**)&wvlo, g_wv_lo);
    cudaGetSymbolAddress((void**)&wohi, g_wo_hi); cudaGetSymbolAddress((void**)&wolo, g_wo_lo);
    cudaGetSymbolAddress((void**)&qhh,  g_qhh);   cudaGetSymbolAddress((void**)&qhl,  g_qhl);
    cudaGetSymbolAddress((void**)&khh,  g_khh);   cudaGetSymbolAddress((void**)&khl,  g_khl);
    cudaGetSymbolAddress((void**)&vhh,  g_vhh);   cudaGetSymbolAddress((void**)&vhl,  g_vhl);
    cudaGetSymbolAddress((void**)&chi,  g_c_hi);  cudaGetSymbolAddress((void**)&clo,  g_c_lo);

    cudaFuncSetAttribute(gemm_mma_kernel,
                         cudaFuncAttributeMaxDynamicSharedMemorySize, GEMM_SMEM);
    cudaFuncSetAttribute(gemm_qkv_kernel,
                         cudaFuncAttributeMaxDynamicSharedMemorySize, GEMM_SMEM);
    cudaFuncSetAttribute(attn_kernel,
                         cudaFuncAttributeMaxDynamicSharedMemorySize, ATT_SMEM);

    // 1) hi/lo conversions
    const int nIn4 = Mq * Dq / 4;
    const int nW4  = Dq * Dq / 4;
    {
        dim3 g3(nIn4 / 256, 1, 3);
        cvt_hilo3_kernel<<<g3, 256>>>(q, k, v, qhi, qlo, khi, klo, vhi, vlo, nIn4);
        dim3 g4(nW4 / 256, 1, 4);
        cvt_hilo4_kernel<<<g4, 256>>>(Wq, Wk, Wv, Wo,
                                      wqhi, wqlo, wkhi, wklo,
                                      wvhi, wvlo, wohi, wolo, nW4);
    }

    // 2) fused QKV projections -> bf16 hi/lo head-split (Q pre-scaled 1/8)
    dim3 qkv_grid(Dq / 128, Mq / 128, 3);
    gemm_qkv_kernel<<<qkv_grid, 256, GEMM_SMEM>>>(
        qhi, qlo, khi, klo, vhi, vlo,
        wqhi, wqlo, wkhi, wklo, wvhi, wvlo,
        qhh, qhl, khh, khl, vhh, vhl);

    // 3) tensor-core flash attention (1024 CTAs, 2/SM) -> ctx hi/lo bf16
    dim3 attn_grid(Sq / 64, Bq * Hq);   // (32, 32) = 1024 CTAs
    attn_kernel<<<attn_grid, 128, ATT_SMEM>>>(
        qhh, qhl, khh, khl, vhh, vhl, am, mf, chi, clo);

    // 4) output projection
    dim3 gemm_grid(Dq / 128, Mq / 128);
    gemm_mma_kernel<<<gemm_grid, 256, GEMM_SMEM>>>(chi, clo, wohi, wolo, out);
}